// round 1
// baseline (speedup 1.0000x reference)
#include <cuda_runtime.h>
#include <math.h>

// Problem dims (fixed)
#define NN    8192
#define INDIM 1024
#define DD    512
#define DHALF 256

// Scratch (device globals: allocation-free rule)
__device__ float g_q[NN * DD];
__device__ float g_k[NN * DD];
__device__ float g_v[NN * DD];
__device__ float g_ctx[NN * DD];
__device__ float g_s[(size_t)NN * NN];   // 256 MB attention logits / probs

// ---------------------------------------------------------------------------
// Generic NN GEMM: C[M x Nc] = A[M x K] @ B[K x Nc] (+ bias), 128x128x8 tile,
// 256 threads, 8x8 accumulator per thread.
// ---------------------------------------------------------------------------
__global__ __launch_bounds__(256) void gemm_nn(
    const float* __restrict__ A, int lda,
    const float* __restrict__ B, int ldb,
    float* __restrict__ C, int ldc,
    int K, const float* __restrict__ bias)
{
    __shared__ float As[8][128];
    __shared__ float Bs[8][128];

    const int tid = threadIdx.x;
    const int tx = tid & 15;        // 0..15 -> 8 cols each
    const int ty = tid >> 4;        // 0..15 -> 8 rows each
    const int rb = blockIdx.y * 128;
    const int cb = blockIdx.x * 128;

    // A tile loader: [128 rows][8 k], stored transposed As[k][row]
    const int arow = tid >> 1;
    const int acol = (tid & 1) * 4;
    // B tile loader: [8 k][128 cols], stored direct Bs[k][col]
    const int brow = tid >> 5;
    const int bcol = (tid & 31) * 4;

    float acc[8][8];
#pragma unroll
    for (int i = 0; i < 8; i++)
#pragma unroll
        for (int j = 0; j < 8; j++) acc[i][j] = 0.f;

    for (int k0 = 0; k0 < K; k0 += 8) {
        float4 av = *(const float4*)&A[(size_t)(rb + arow) * lda + k0 + acol];
        float4 bv = *(const float4*)&B[(size_t)(k0 + brow) * ldb + cb + bcol];
        __syncthreads();
        As[acol + 0][arow] = av.x;
        As[acol + 1][arow] = av.y;
        As[acol + 2][arow] = av.z;
        As[acol + 3][arow] = av.w;
        *(float4*)&Bs[brow][bcol] = bv;
        __syncthreads();
#pragma unroll
        for (int kk = 0; kk < 8; kk++) {
            float a[8], b[8];
            *(float4*)&a[0] = *(const float4*)&As[kk][ty * 8 + 0];
            *(float4*)&a[4] = *(const float4*)&As[kk][ty * 8 + 4];
            *(float4*)&b[0] = *(const float4*)&Bs[kk][tx * 8 + 0];
            *(float4*)&b[4] = *(const float4*)&Bs[kk][tx * 8 + 4];
#pragma unroll
            for (int i = 0; i < 8; i++)
#pragma unroll
                for (int j = 0; j < 8; j++)
                    acc[i][j] = fmaf(a[i], b[j], acc[i][j]);
        }
    }

    float bj[8];
#pragma unroll
    for (int j = 0; j < 8; j++) bj[j] = bias ? bias[cb + tx * 8 + j] : 0.f;

#pragma unroll
    for (int i = 0; i < 8; i++) {
        float out0[4], out1[4];
#pragma unroll
        for (int j = 0; j < 4; j++) { out0[j] = acc[i][j] + bj[j]; out1[j] = acc[i][j + 4] + bj[j + 4]; }
        float* crow = &C[(size_t)(rb + ty * 8 + i) * ldc + cb + tx * 8];
        *(float4*)&crow[0] = *(float4*)out0;
        *(float4*)&crow[4] = *(float4*)out1;
    }
}

// ---------------------------------------------------------------------------
// NT GEMM with scale: S[M x Nc] = scale * (Q[M x K] @ K[Nc x K]^T)
// Same tiling; both operands loaded transposed into smem.
// ---------------------------------------------------------------------------
__global__ __launch_bounds__(256) void gemm_nt_scaled(
    const float* __restrict__ A,   // Q, ld = DD
    const float* __restrict__ Bm,  // K, ld = DD
    float* __restrict__ C,         // S, ld = NN
    int K, float scale)
{
    __shared__ float As[8][128];
    __shared__ float Bs[8][128];

    const int tid = threadIdx.x;
    const int tx = tid & 15;
    const int ty = tid >> 4;
    const int rb = blockIdx.y * 128;
    const int cb = blockIdx.x * 128;

    const int arow = tid >> 1;
    const int acol = (tid & 1) * 4;

    float acc[8][8];
#pragma unroll
    for (int i = 0; i < 8; i++)
#pragma unroll
        for (int j = 0; j < 8; j++) acc[i][j] = 0.f;

    for (int k0 = 0; k0 < K; k0 += 8) {
        float4 av = *(const float4*)&A[(size_t)(rb + arow) * DD + k0 + acol];
        float4 bv = *(const float4*)&Bm[(size_t)(cb + arow) * DD + k0 + acol];
        __syncthreads();
        As[acol + 0][arow] = av.x;
        As[acol + 1][arow] = av.y;
        As[acol + 2][arow] = av.z;
        As[acol + 3][arow] = av.w;
        Bs[acol + 0][arow] = bv.x;
        Bs[acol + 1][arow] = bv.y;
        Bs[acol + 2][arow] = bv.z;
        Bs[acol + 3][arow] = bv.w;
        __syncthreads();
#pragma unroll
        for (int kk = 0; kk < 8; kk++) {
            float a[8], b[8];
            *(float4*)&a[0] = *(const float4*)&As[kk][ty * 8 + 0];
            *(float4*)&a[4] = *(const float4*)&As[kk][ty * 8 + 4];
            *(float4*)&b[0] = *(const float4*)&Bs[kk][tx * 8 + 0];
            *(float4*)&b[4] = *(const float4*)&Bs[kk][tx * 8 + 4];
#pragma unroll
            for (int i = 0; i < 8; i++)
#pragma unroll
                for (int j = 0; j < 8; j++)
                    acc[i][j] = fmaf(a[i], b[j], acc[i][j]);
        }
    }

#pragma unroll
    for (int i = 0; i < 8; i++) {
        float out0[4], out1[4];
#pragma unroll
        for (int j = 0; j < 4; j++) { out0[j] = acc[i][j] * scale; out1[j] = acc[i][j + 4] * scale; }
        float* crow = &C[(size_t)(rb + ty * 8 + i) * NN + cb + tx * 8];
        *(float4*)&crow[0] = *(float4*)out0;
        *(float4*)&crow[4] = *(float4*)out1;
    }
}

// ---------------------------------------------------------------------------
// Row softmax over g_s, in place. One block (256 threads) per row of 8192.
// ---------------------------------------------------------------------------
__global__ __launch_bounds__(256) void softmax_rows()
{
    const int row = blockIdx.x;
    const int t = threadIdx.x;
    float* s = g_s + (size_t)row * NN;
    __shared__ float red[256];

    float m = -1e30f;
    for (int i = t; i < NN; i += 256) m = fmaxf(m, s[i]);
    red[t] = m; __syncthreads();
    for (int w = 128; w > 0; w >>= 1) {
        if (t < w) red[t] = fmaxf(red[t], red[t + w]);
        __syncthreads();
    }
    m = red[0]; __syncthreads();

    float sum = 0.f;
    for (int i = t; i < NN; i += 256) {
        float e = expf(s[i] - m);
        s[i] = e;
        sum += e;
    }
    red[t] = sum; __syncthreads();
    for (int w = 128; w > 0; w >>= 1) {
        if (t < w) red[t] += red[t + w];
        __syncthreads();
    }
    const float inv = 1.f / red[0];

    for (int i = t; i < NN; i += 256) s[i] *= inv;
}

// ---------------------------------------------------------------------------
// MLP head: per row, h = relu(ctx @ W1 + b1) [256], score = h @ W2 + b2.
// One block (256 threads) per row.
// ---------------------------------------------------------------------------
__global__ __launch_bounds__(256) void mlp_head(
    const float* __restrict__ W1, const float* __restrict__ b1,
    const float* __restrict__ W2, const float* __restrict__ b2,
    float* __restrict__ out)
{
    const int row = blockIdx.x;
    const int t = threadIdx.x;
    __shared__ float xs[DD];
    __shared__ float red[256];

    const float* c = g_ctx + (size_t)row * DD;
    xs[t] = c[t];
    xs[t + 256] = c[t + 256];
    __syncthreads();

    float acc = b1[t];
#pragma unroll 8
    for (int k = 0; k < DD; k++)
        acc = fmaf(xs[k], W1[k * DHALF + t], acc);
    float h = fmaxf(acc, 0.f);

    red[t] = h * W2[t];
    __syncthreads();
    for (int w = 128; w > 0; w >>= 1) {
        if (t < w) red[t] += red[t + w];
        __syncthreads();
    }
    if (t == 0) out[row] = red[0] + b2[0];
}

// ---------------------------------------------------------------------------
extern "C" void kernel_launch(void* const* d_in, const int* in_sizes, int n_in,
                              void* d_out, int out_size)
{
    const float* x  = (const float*)d_in[0];
    const float* Wq = (const float*)d_in[1];
    const float* bq = (const float*)d_in[2];
    const float* Wk = (const float*)d_in[3];
    const float* bk = (const float*)d_in[4];
    const float* Wv = (const float*)d_in[5];
    const float* bv = (const float*)d_in[6];
    const float* W1 = (const float*)d_in[7];
    const float* b1 = (const float*)d_in[8];
    const float* W2 = (const float*)d_in[9];
    const float* b2 = (const float*)d_in[10];
    float* out = (float*)d_out;

    float *pq, *pk, *pv, *ps, *pctx;
    cudaGetSymbolAddress((void**)&pq,  g_q);
    cudaGetSymbolAddress((void**)&pk,  g_k);
    cudaGetSymbolAddress((void**)&pv,  g_v);
    cudaGetSymbolAddress((void**)&ps,  g_s);
    cudaGetSymbolAddress((void**)&pctx, g_ctx);

    // QKV projections: [8192,1024] @ [1024,512] + bias
    {
        dim3 grid(DD / 128, NN / 128);
        gemm_nn<<<grid, 256>>>(x, INDIM, Wq, DD, pq, DD, INDIM, bq);
        gemm_nn<<<grid, 256>>>(x, INDIM, Wk, DD, pk, DD, INDIM, bk);
        gemm_nn<<<grid, 256>>>(x, INDIM, Wv, DD, pv, DD, INDIM, bv);
    }

    // S = (Q @ K^T) / sqrt(D)
    {
        dim3 grid(NN / 128, NN / 128);
        const float scale = 1.0f / sqrtf((float)DD);
        gemm_nt_scaled<<<grid, 256>>>(pq, pk, ps, DD, scale);
    }

    // softmax rows in place
    softmax_rows<<<NN, 256>>>();

    // ctx = P @ V : [8192,8192] @ [8192,512]
    {
        dim3 grid(DD / 128, NN / 128);
        gemm_nn<<<grid, 256>>>(ps, NN, pv, DD, pctx, DD, NN, nullptr);
    }

    // MLP head
    mlp_head<<<NN, 256>>>(W1, b1, W2, b2, out);
}

// round 2
// speedup vs baseline: 2.9038x; 2.9038x over previous
#include <cuda_runtime.h>
#include <math.h>

#define NN    8192
#define INDIM 1024
#define DD    512
#define DHALF 256

// Scratch (device globals: allocation-free rule)
__device__ float g_q[NN * DD];
__device__ float g_k[NN * DD];
__device__ float g_v[NN * DD];
__device__ float g_vp[NN * DHALF];            // V @ W1
__device__ float g_h[NN * DHALF];             // relu(P @ V' + b1)
__device__ float g_s[(size_t)NN * NN];        // 256 MB attention logits / probs

// round-to-nearest fp32 -> tf32 (kept in 32-bit container)
__device__ __forceinline__ unsigned f2t(float x) {
    unsigned u;
    asm("cvt.rna.tf32.f32 %0, %1;" : "=r"(u) : "f"(x));
    return u;
}

__device__ __forceinline__ void mma8(float* d, const unsigned* a, const unsigned* b) {
    asm volatile(
        "mma.sync.aligned.m16n8k8.row.col.f32.tf32.tf32.f32 "
        "{%0,%1,%2,%3}, {%4,%5,%6,%7}, {%8,%9}, {%0,%1,%2,%3};\n"
        : "+f"(d[0]), "+f"(d[1]), "+f"(d[2]), "+f"(d[3])
        : "r"(a[0]), "r"(a[1]), "r"(a[2]), "r"(a[3]), "r"(b[0]), "r"(b[1]));
}

// ---------------------------------------------------------------------------
// tf32 tensor-core GEMM.
//   C[M x Nc] = scale * (A[M x K] @ B) + bias, optional relu.
//   Block tile: MT x 256, k-step 16. 8 warps (2 x 4), warp tile (MT/2) x 64.
//   BT=false: B is [K][Nc] row-major (ld=ldb).
//   BT=true : B logical [K][Nc] but gmem holds Bg[Nc][K] (ld=ldb)  (Q@K^T).
// ---------------------------------------------------------------------------
template<int MT, bool BT>
__global__ __launch_bounds__(256) void gemm_tc(
    const float* __restrict__ A, int lda,
    const float* __restrict__ B, int ldb,
    float* __restrict__ C, int ldc,
    int K, const float* __restrict__ bias, float scale, int relu)
{
    constexpr int AST = 20;    // As row stride (16 k + 4 pad): conflict-free frag reads
    constexpr int BST = 264;   // Bs row stride (256 n + 8 pad)
    constexpr int MW  = MT / 2;     // rows per warp
    constexpr int NMT = MW / 16;    // m16 tiles per warp

    __shared__ float As[MT * AST];
    __shared__ float Bs[16 * BST];

    const int tid  = threadIdx.x;
    const int lane = tid & 31;
    const int warp = tid >> 5;
    const int wm   = warp >> 2;    // 0..1
    const int wn   = warp & 3;     // 0..3
    const int gid  = lane >> 2;    // 0..7
    const int tig  = lane & 3;     // 0..3
    const int rb   = blockIdx.y * MT;
    const int cb   = blockIdx.x * 256;

    float acc[NMT][8][4];
#pragma unroll
    for (int mt = 0; mt < NMT; mt++)
#pragma unroll
        for (int nt = 0; nt < 8; nt++)
#pragma unroll
            for (int i = 0; i < 4; i++) acc[mt][nt][i] = 0.f;

    float4 pa[MT / 64];
    float4 pb[4];

    auto loadA = [&](int k0) {
#pragma unroll
        for (int i = 0; i < MT / 64; i++) {
            int q = tid + i * 256;
            int r = q >> 2, kq = (q & 3) * 4;
            pa[i] = *(const float4*)&A[(size_t)(rb + r) * lda + k0 + kq];
        }
    };
    auto loadB = [&](int k0) {
#pragma unroll
        for (int i = 0; i < 4; i++) {
            int q = tid + i * 256;
            if (BT) {
                int n = q & 255, kq = (q >> 8) * 4;
                pb[i] = *(const float4*)&B[(size_t)(cb + n) * ldb + k0 + kq];
            } else {
                int r = q >> 6, c = (q & 63) * 4;
                pb[i] = *(const float4*)&B[(size_t)(k0 + r) * ldb + cb + c];
            }
        }
    };
    auto storeAB = [&]() {
#pragma unroll
        for (int i = 0; i < MT / 64; i++) {
            int q = tid + i * 256;
            int r = q >> 2, kq = (q & 3) * 4;
            float4 t;
            t.x = __uint_as_float(f2t(pa[i].x));
            t.y = __uint_as_float(f2t(pa[i].y));
            t.z = __uint_as_float(f2t(pa[i].z));
            t.w = __uint_as_float(f2t(pa[i].w));
            *(float4*)&As[r * AST + kq] = t;
        }
#pragma unroll
        for (int i = 0; i < 4; i++) {
            int q = tid + i * 256;
            if (BT) {
                int n = q & 255, kq = (q >> 8) * 4;
                Bs[(kq + 0) * BST + n] = __uint_as_float(f2t(pb[i].x));
                Bs[(kq + 1) * BST + n] = __uint_as_float(f2t(pb[i].y));
                Bs[(kq + 2) * BST + n] = __uint_as_float(f2t(pb[i].z));
                Bs[(kq + 3) * BST + n] = __uint_as_float(f2t(pb[i].w));
            } else {
                int r = q >> 6, c = (q & 63) * 4;
                float4 t;
                t.x = __uint_as_float(f2t(pb[i].x));
                t.y = __uint_as_float(f2t(pb[i].y));
                t.z = __uint_as_float(f2t(pb[i].z));
                t.w = __uint_as_float(f2t(pb[i].w));
                *(float4*)&Bs[r * BST + c] = t;
            }
        }
    };
    auto compute = [&]() {
        const unsigned* Asu = (const unsigned*)As;
        const unsigned* Bsu = (const unsigned*)Bs;
#pragma unroll
        for (int kk = 0; kk < 16; kk += 8) {
            unsigned af[NMT][4], bf[8][2];
#pragma unroll
            for (int mt = 0; mt < NMT; mt++) {
                int r0 = wm * MW + mt * 16 + gid;
                af[mt][0] = Asu[r0 * AST + kk + tig];
                af[mt][1] = Asu[(r0 + 8) * AST + kk + tig];
                af[mt][2] = Asu[r0 * AST + kk + tig + 4];
                af[mt][3] = Asu[(r0 + 8) * AST + kk + tig + 4];
            }
#pragma unroll
            for (int nt = 0; nt < 8; nt++) {
                int c0 = wn * 64 + nt * 8 + gid;
                bf[nt][0] = Bsu[(kk + tig) * BST + c0];
                bf[nt][1] = Bsu[(kk + tig + 4) * BST + c0];
            }
#pragma unroll
            for (int mt = 0; mt < NMT; mt++)
#pragma unroll
                for (int nt = 0; nt < 8; nt++)
                    mma8(acc[mt][nt], af[mt], bf[nt]);
        }
    };

    loadA(0);
    loadB(0);
    storeAB();
    __syncthreads();

    for (int k0 = 16;; k0 += 16) {
        bool last = (k0 >= K);
        if (!last) { loadA(k0); loadB(k0); }
        compute();
        if (last) break;
        __syncthreads();
        storeAB();
        __syncthreads();
    }

    // epilogue
#pragma unroll
    for (int mt = 0; mt < NMT; mt++) {
#pragma unroll
        for (int nt = 0; nt < 8; nt++) {
            int r0 = rb + wm * MW + mt * 16 + gid;
            int c0 = cb + wn * 64 + nt * 8 + 2 * tig;
            float b0 = bias ? bias[c0] : 0.f;
            float b1v = bias ? bias[c0 + 1] : 0.f;
            float v0 = acc[mt][nt][0] * scale + b0;
            float v1 = acc[mt][nt][1] * scale + b1v;
            float v2 = acc[mt][nt][2] * scale + b0;
            float v3 = acc[mt][nt][3] * scale + b1v;
            if (relu) {
                v0 = fmaxf(v0, 0.f); v1 = fmaxf(v1, 0.f);
                v2 = fmaxf(v2, 0.f); v3 = fmaxf(v3, 0.f);
            }
            *(float2*)&C[(size_t)r0 * ldc + c0]       = make_float2(v0, v1);
            *(float2*)&C[(size_t)(r0 + 8) * ldc + c0] = make_float2(v2, v3);
        }
    }
}

// ---------------------------------------------------------------------------
// Row softmax over g_s, in place. One block (256 threads) per row.
// ---------------------------------------------------------------------------
__global__ __launch_bounds__(256) void softmax_rows()
{
    const int row = blockIdx.x;
    const int t = threadIdx.x;
    float* s = g_s + (size_t)row * NN;
    __shared__ float red[256];

    float m = -1e30f;
    for (int i = t; i < NN; i += 256) m = fmaxf(m, s[i]);
    red[t] = m; __syncthreads();
    for (int w = 128; w > 0; w >>= 1) {
        if (t < w) red[t] = fmaxf(red[t], red[t + w]);
        __syncthreads();
    }
    m = red[0]; __syncthreads();

    float sum = 0.f;
    for (int i = t; i < NN; i += 256) {
        float e = expf(s[i] - m);
        s[i] = e;
        sum += e;
    }
    red[t] = sum; __syncthreads();
    for (int w = 128; w > 0; w >>= 1) {
        if (t < w) red[t] += red[t + w];
        __syncthreads();
    }
    const float inv = 1.f / red[0];
    for (int i = t; i < NN; i += 256) s[i] *= inv;
}

// ---------------------------------------------------------------------------
// scores = h @ W2 + b2, one block per row (h already relu'd with b1 applied)
// ---------------------------------------------------------------------------
__global__ __launch_bounds__(256) void score_head(
    const float* __restrict__ W2, const float* __restrict__ b2,
    float* __restrict__ out)
{
    const int row = blockIdx.x;
    const int t = threadIdx.x;
    __shared__ float red[256];
    red[t] = g_h[(size_t)row * DHALF + t] * W2[t];
    __syncthreads();
    for (int w = 128; w > 0; w >>= 1) {
        if (t < w) red[t] += red[t + w];
        __syncthreads();
    }
    if (t == 0) out[row] = red[0] + b2[0];
}

// ---------------------------------------------------------------------------
extern "C" void kernel_launch(void* const* d_in, const int* in_sizes, int n_in,
                              void* d_out, int out_size)
{
    const float* x  = (const float*)d_in[0];
    const float* Wq = (const float*)d_in[1];
    const float* bq = (const float*)d_in[2];
    const float* Wk = (const float*)d_in[3];
    const float* bk = (const float*)d_in[4];
    const float* Wv = (const float*)d_in[5];
    const float* bv = (const float*)d_in[6];
    const float* W1 = (const float*)d_in[7];
    const float* b1 = (const float*)d_in[8];
    const float* W2 = (const float*)d_in[9];
    const float* b2 = (const float*)d_in[10];
    float* out = (float*)d_out;

    float *pq, *pk, *pv, *ps, *pvp;
    cudaGetSymbolAddress((void**)&pq,  g_q);
    cudaGetSymbolAddress((void**)&pk,  g_k);
    cudaGetSymbolAddress((void**)&pv,  g_v);
    cudaGetSymbolAddress((void**)&ps,  g_s);
    cudaGetSymbolAddress((void**)&pvp, g_vp);
    float* ph;
    cudaGetSymbolAddress((void**)&ph,  g_h);

    const float scale = 1.0f / sqrtf((float)DD);

    // QKV projections: [8192,1024] @ [1024,512] + bias
    {
        dim3 grid(DD / 256, NN / 128);
        gemm_tc<128, false><<<grid, 256>>>(x, INDIM, Wq, DD, pq, DD, INDIM, bq, 1.f, 0);
        gemm_tc<128, false><<<grid, 256>>>(x, INDIM, Wk, DD, pk, DD, INDIM, bk, 1.f, 0);
        gemm_tc<128, false><<<grid, 256>>>(x, INDIM, Wv, DD, pv, DD, INDIM, bv, 1.f, 0);
    }

    // V' = V @ W1 : [8192,512] @ [512,256]
    {
        dim3 grid(DHALF / 256, NN / 64);
        gemm_tc<64, false><<<grid, 256>>>(pv, DD, W1, DHALF, pvp, DHALF, DD, nullptr, 1.f, 0);
    }

    // S = (Q @ K^T) * scale : [8192,512] @ [512,8192]^T
    {
        dim3 grid(NN / 256, NN / 128);
        gemm_tc<128, true><<<grid, 256>>>(pq, DD, pk, DD, ps, NN, DD, nullptr, scale, 0);
    }

    softmax_rows<<<NN, 256>>>();

    // h = relu(P @ V' + b1) : [8192,8192] @ [8192,256]
    {
        dim3 grid(DHALF / 256, NN / 64);
        gemm_tc<64, false><<<grid, 256>>>(ps, NN, pvp, DHALF, ph, DHALF, NN, b1, 1.f, 1);
    }

    score_head<<<NN, 256>>>(W2, b2, out);
}

// round 4
// speedup vs baseline: 4.2751x; 1.4723x over previous
#include <cuda_runtime.h>
#include <math.h>

#define NN    8192
#define INDIM 1024
#define DD    512
#define DHALF 256

// ------------------------- scratch (device globals) -------------------------
__device__ float g_xt[NN * INDIM];            // tf32-rounded x
__device__ float g_wqkv[INDIM * 1536];        // packed [Wq|Wk|Wv], tf32
__device__ float g_bqkv[1536];
__device__ float g_w1t[DD * DHALF];           // tf32 W1
__device__ float g_qkv[NN * 1536];            // q|k|v, tf32 (ld=1536)
__device__ float g_vp[NN * DHALF];            // V @ W1, tf32
__device__ float g_s[(size_t)NN * NN];        // E = exp(S/sqrt(D)), tf32
__device__ float g_r[NN];                     // row sums of E
__device__ float g_u[8 * (size_t)NN * DHALF]; // split-K partials of E @ V'

// fp32 -> tf32 round-to-nearest (kept in 32-bit container)
__device__ __forceinline__ float f2t(float x) {
    unsigned u;
    asm("cvt.rna.tf32.f32 %0, %1;" : "=r"(u) : "f"(x));
    return __uint_as_float(u);
}

__device__ __forceinline__ void mma8(float* d, const unsigned* a, const unsigned* b) {
    asm volatile(
        "mma.sync.aligned.m16n8k8.row.col.f32.tf32.tf32.f32 "
        "{%0,%1,%2,%3}, {%4,%5,%6,%7}, {%8,%9}, {%0,%1,%2,%3};\n"
        : "+f"(d[0]), "+f"(d[1]), "+f"(d[2]), "+f"(d[3])
        : "r"(a[0]), "r"(a[1]), "r"(a[2]), "r"(a[3]), "r"(b[0]), "r"(b[1]));
}

__device__ __forceinline__ void cpa16(float* dst, const float* src) {
    unsigned d = (unsigned)__cvta_generic_to_shared(dst);
    asm volatile("cp.async.cg.shared.global [%0], [%1], 16;\n" :: "r"(d), "l"(src));
}
#define CP_COMMIT()  asm volatile("cp.async.commit_group;\n" ::: "memory")
#define CP_WAIT2()   asm volatile("cp.async.wait_group 2;\n" ::: "memory")

// ---------------------------------------------------------------------------
// tf32 GEMM, cp.async 3-stage pipeline.
//   Tile 128x256, kTile 32, 256 threads (8 warps, warp tile 64x64).
//   BT=false: B[K][Nc] row-major.  BT=true: gmem holds B[Nc][K] (Q@K^T).
//   EPI: 0 = f2t(scale*acc + bias)   1 = f2t(expf(scale*acc))   2 = raw acc
//   Split-K via blockIdx.z: k-window = [z*Kchunk, (z+1)*Kchunk),
//   C plane offset z*c_split.
// ---------------------------------------------------------------------------
#define AST  36    // As row stride (32 k + 4 pad)
#define BSTN 264   // Bs row stride, !BT layout [k][n]
#define BSTT 36    // Bs row stride, BT layout [n][k]
#define ASTG (128 * AST)

static_assert(3 * (ASTG + 32 * BSTN) * 4 <= 227 * 1024, "smem NB");
static_assert(3 * (ASTG + 256 * BSTT) * 4 <= 227 * 1024, "smem BT");

template<bool BT, int EPI>
__global__ __launch_bounds__(256, 1) void gemm_tc2(
    const float* __restrict__ A, int lda,
    const float* __restrict__ B, int ldb,
    float* __restrict__ C, int ldc, size_t c_split,
    int Kchunk, const float* __restrict__ bias, float scale)
{
    extern __shared__ float sm[];
    float* Asm = sm;
    float* Bsm = sm + 3 * ASTG;
    constexpr int BSTG = BT ? (256 * BSTT) : (32 * BSTN);

    const int tid  = threadIdx.x;
    const int lane = tid & 31;
    const int warp = tid >> 5;
    const int wm   = warp >> 2;        // 0..1
    const int wn   = warp & 3;         // 0..3
    const int gid  = lane >> 2;        // 0..7
    const int tig  = lane & 3;         // 0..3
    const int rb   = blockIdx.y * 128;
    const int cb   = blockIdx.x * 256;
    const int kbase = blockIdx.z * Kchunk;

    float acc[4][8][4];
#pragma unroll
    for (int mt = 0; mt < 4; mt++)
#pragma unroll
        for (int nt = 0; nt < 8; nt++)
#pragma unroll
            for (int i = 0; i < 4; i++) acc[mt][nt][i] = 0.f;

    auto issueLoads = [&](int slot, int k0) {
        float* As = Asm + slot * ASTG;
        float* Bs = Bsm + slot * BSTG;
#pragma unroll
        for (int i = 0; i < 4; i++) {           // A: 128x32
            int q = tid + i * 256;
            int r = q >> 3, c = (q & 7) * 4;
            cpa16(&As[r * AST + c], &A[(size_t)(rb + r) * lda + kbase + k0 + c]);
        }
        if (BT) {
#pragma unroll
            for (int i = 0; i < 8; i++) {       // B: 256 n-rows x 32 k
                int q = tid + i * 256;
                int n = q >> 3, c = (q & 7) * 4;
                cpa16(&Bs[n * BSTT + c], &B[(size_t)(cb + n) * ldb + kbase + k0 + c]);
            }
        } else {
#pragma unroll
            for (int i = 0; i < 8; i++) {       // B: 32 k-rows x 256 n
                int q = tid + i * 256;
                int r = q >> 6, c = (q & 63) * 4;
                cpa16(&Bs[r * BSTN + c], &B[(size_t)(kbase + k0 + r) * ldb + cb + c]);
            }
        }
    };

    const int NITER = Kchunk / 32;
    issueLoads(0, 0);  CP_COMMIT();
    issueLoads(1, 32); CP_COMMIT();
    issueLoads(2, 64); CP_COMMIT();

    for (int it = 0; it < NITER; ++it) {
        CP_WAIT2();
        __syncthreads();
        {
            const unsigned* Asu = (const unsigned*)(Asm + (it % 3) * ASTG);
            const unsigned* Bsu = (const unsigned*)(Bsm + (it % 3) * BSTG);
#pragma unroll
            for (int kk = 0; kk < 32; kk += 8) {
                unsigned af[4][4], bf[8][2];
#pragma unroll
                for (int mt = 0; mt < 4; mt++) {
                    int r0 = wm * 64 + mt * 16 + gid;
                    af[mt][0] = Asu[r0 * AST + kk + tig];
                    af[mt][1] = Asu[(r0 + 8) * AST + kk + tig];
                    af[mt][2] = Asu[r0 * AST + kk + tig + 4];
                    af[mt][3] = Asu[(r0 + 8) * AST + kk + tig + 4];
                }
#pragma unroll
                for (int nt = 0; nt < 8; nt++) {
                    int c0 = wn * 64 + nt * 8 + gid;
                    if (BT) {
                        bf[nt][0] = Bsu[c0 * BSTT + kk + tig];
                        bf[nt][1] = Bsu[c0 * BSTT + kk + tig + 4];
                    } else {
                        bf[nt][0] = Bsu[(kk + tig) * BSTN + c0];
                        bf[nt][1] = Bsu[(kk + tig + 4) * BSTN + c0];
                    }
                }
#pragma unroll
                for (int mt = 0; mt < 4; mt++)
#pragma unroll
                    for (int nt = 0; nt < 8; nt++)
                        mma8(acc[mt][nt], af[mt], bf[nt]);
            }
        }
        __syncthreads();
        int nx = it + 3;
        if (nx < NITER) issueLoads(nx % 3, nx * 32);
        CP_COMMIT();
    }

    // epilogue
    float* Cz = C + blockIdx.z * c_split;
#pragma unroll
    for (int mt = 0; mt < 4; mt++) {
#pragma unroll
        for (int nt = 0; nt < 8; nt++) {
            int r0 = rb + wm * 64 + mt * 16 + gid;
            int c0 = cb + wn * 64 + nt * 8 + 2 * tig;
            float v0 = acc[mt][nt][0], v1 = acc[mt][nt][1];
            float v2 = acc[mt][nt][2], v3 = acc[mt][nt][3];
            if (EPI == 0) {
                float b0 = bias ? bias[c0] : 0.f;
                float b1v = bias ? bias[c0 + 1] : 0.f;
                v0 = f2t(v0 * scale + b0);  v1 = f2t(v1 * scale + b1v);
                v2 = f2t(v2 * scale + b0);  v3 = f2t(v3 * scale + b1v);
            } else if (EPI == 1) {
                v0 = f2t(__expf(v0 * scale)); v1 = f2t(__expf(v1 * scale));
                v2 = f2t(__expf(v2 * scale)); v3 = f2t(__expf(v3 * scale));
            }
            *(float2*)&Cz[(size_t)r0 * ldc + c0]       = make_float2(v0, v1);
            *(float2*)&Cz[(size_t)(r0 + 8) * ldc + c0] = make_float2(v2, v3);
        }
    }
}

// --------------------------- aux kernels -----------------------------------
__global__ void xprep(const float* __restrict__ x, float* __restrict__ o, int n4)
{
    int i = blockIdx.x * blockDim.x + threadIdx.x;
    if (i < n4) {
        float4 v = ((const float4*)x)[i];
        v.x = f2t(v.x); v.y = f2t(v.y); v.z = f2t(v.z); v.w = f2t(v.w);
        ((float4*)o)[i] = v;
    }
}

__global__ void pack_qkv(const float* __restrict__ Wq, const float* __restrict__ Wk,
                         const float* __restrict__ Wv,
                         const float* __restrict__ bq, const float* __restrict__ bk,
                         const float* __restrict__ bv)
{
    int i = blockIdx.x * blockDim.x + threadIdx.x;
    int total = INDIM * 1536;
    if (i < total) {
        int row = i / 1536, col = i % 1536;
        float v = (col < 512) ? Wq[row * 512 + col]
               : (col < 1024) ? Wk[row * 512 + col - 512]
                              : Wv[row * 512 + col - 1024];
        g_wqkv[i] = f2t(v);
    }
    if (i < 1536) {
        g_bqkv[i] = (i < 512) ? bq[i] : (i < 1024) ? bk[i - 512] : bv[i - 1024];
    }
}

__global__ void pack_w1(const float* __restrict__ W1)
{
    int i = blockIdx.x * blockDim.x + threadIdx.x;
    if (i < DD * DHALF) g_w1t[i] = f2t(W1[i]);
}

// row sums of E (one block per row)
__global__ __launch_bounds__(256) void rowsum()
{
    const int row = blockIdx.x;
    const int t = threadIdx.x;
    const float4* e = (const float4*)(g_s + (size_t)row * NN);
    __shared__ float red[256];
    float s = 0.f;
#pragma unroll
    for (int i = 0; i < NN / 4 / 256; i++) {
        float4 v = e[t + i * 256];
        s += (v.x + v.y) + (v.z + v.w);
    }
    red[t] = s; __syncthreads();
    for (int w = 128; w > 0; w >>= 1) {
        if (t < w) red[t] += red[t + w];
        __syncthreads();
    }
    if (t == 0) g_r[row] = red[0];
}

// sum split-K partials, normalize, relu(+b1), dot with W2 -> score
__global__ __launch_bounds__(256) void pv_reduce_score(
    const float* __restrict__ b1, const float* __restrict__ W2,
    const float* __restrict__ b2, float* __restrict__ out)
{
    const int row = blockIdx.x;
    const int t = threadIdx.x;
    __shared__ float red[256];
    float s = 0.f;
#pragma unroll
    for (int z = 0; z < 8; z++)
        s += g_u[(size_t)z * NN * DHALF + (size_t)row * DHALF + t];
    float h = fmaxf(s / g_r[row] + b1[t], 0.f);
    red[t] = h * W2[t];
    __syncthreads();
    for (int w = 128; w > 0; w >>= 1) {
        if (t < w) red[t] += red[t + w];
        __syncthreads();
    }
    if (t == 0) out[row] = red[0] + b2[0];
}

// ---------------------------------------------------------------------------
extern "C" void kernel_launch(void* const* d_in, const int* in_sizes, int n_in,
                              void* d_out, int out_size)
{
    const float* x  = (const float*)d_in[0];
    const float* Wq = (const float*)d_in[1];
    const float* bq = (const float*)d_in[2];
    const float* Wk = (const float*)d_in[3];
    const float* bk = (const float*)d_in[4];
    const float* Wv = (const float*)d_in[5];
    const float* bv = (const float*)d_in[6];
    const float* W1 = (const float*)d_in[7];
    const float* b1 = (const float*)d_in[8];
    const float* W2 = (const float*)d_in[9];
    const float* b2 = (const float*)d_in[10];
    float* out = (float*)d_out;

    float *pxt, *pwqkv, *pqkv, *pvp, *ps, *pu;
    cudaGetSymbolAddress((void**)&pxt,   g_xt);
    cudaGetSymbolAddress((void**)&pwqkv, g_wqkv);
    cudaGetSymbolAddress((void**)&pqkv,  g_qkv);
    cudaGetSymbolAddress((void**)&pvp,   g_vp);
    cudaGetSymbolAddress((void**)&ps,    g_s);
    cudaGetSymbolAddress((void**)&pu,    g_u);
    float* pw1t;
    cudaGetSymbolAddress((void**)&pw1t,  g_w1t);
    float* pbqkv;
    cudaGetSymbolAddress((void**)&pbqkv, g_bqkv);

    const int SMEM_NB = 3 * (ASTG + 32 * BSTN) * 4;   // 156672
    const int SMEM_BT = 3 * (ASTG + 256 * BSTT) * 4;  // 165888
    cudaFuncSetAttribute(gemm_tc2<false, 0>, cudaFuncAttributeMaxDynamicSharedMemorySize, SMEM_NB);
    cudaFuncSetAttribute(gemm_tc2<false, 2>, cudaFuncAttributeMaxDynamicSharedMemorySize, SMEM_NB);
    cudaFuncSetAttribute(gemm_tc2<true, 1>,  cudaFuncAttributeMaxDynamicSharedMemorySize, SMEM_BT);

    const float scale = 1.0f / sqrtf((float)DD);

    // input prep
    xprep<<<(NN * INDIM / 4 + 255) / 256, 256>>>(x, pxt, NN * INDIM / 4);
    pack_qkv<<<(INDIM * 1536 + 255) / 256, 256>>>(Wq, Wk, Wv, bq, bk, bv);
    pack_w1<<<(DD * DHALF + 255) / 256, 256>>>(W1);

    // fused QKV: [8192,1024] @ [1024,1536] + bias
    gemm_tc2<false, 0><<<dim3(6, 64), 256, SMEM_NB>>>(
        pxt, INDIM, pwqkv, 1536, pqkv, 1536, 0, INDIM, pbqkv, 1.f);

    // V' = V @ W1 : [8192,512] @ [512,256]
    gemm_tc2<false, 0><<<dim3(1, 64), 256, SMEM_NB>>>(
        pqkv + 1024, 1536, pw1t, DHALF, pvp, DHALF, 0, DD, nullptr, 1.f);

    // E = exp((Q @ K^T) * scale)
    gemm_tc2<true, 1><<<dim3(32, 64), 256, SMEM_BT>>>(
        pqkv, 1536, pqkv + 512, 1536, ps, NN, 0, DD, nullptr, scale);

    rowsum<<<NN, 256>>>();

    // U_z = E[:, z*1024:(z+1)*1024] @ V'[z*1024:(z+1)*1024, :]
    gemm_tc2<false, 2><<<dim3(1, 64, 8), 256, SMEM_NB>>>(
        ps, NN, pvp, DHALF, pu, DHALF, (size_t)NN * DHALF, 1024, nullptr, 1.f);

    pv_reduce_score<<<NN, 256>>>(b1, W2, b2, out);
}

// round 5
// speedup vs baseline: 6.5296x; 1.5273x over previous
#include <cuda_runtime.h>
#include <cuda_fp16.h>
#include <math.h>

#define NN    8192
#define INDIM 1024
#define DD    512
#define DHALF 256

// ------------------------- scratch (device globals) -------------------------
__device__ __half g_xh[NN * INDIM];             // fp16 x
__device__ __half g_wqkvT[1536 * INDIM];        // [n][k] packed [Wq|Wk|Wv]^T
__device__ float  g_bqkv[1536];
__device__ __half g_w1T[DHALF * DD];            // W1^T [256][512]
__device__ __half g_qkvh[NN * 1536];            // q|k|v fp16 (ld=1536)
__device__ __half g_vpT[DHALF * NN];            // (V @ W1)^T  [256][8192]
__device__ __half g_eh[(size_t)NN * NN];        // E = exp(S/sqrt(D)) fp16, 128MB
__device__ float  g_r[NN];                      // row sums of E
__device__ float  g_u[8 * (size_t)NN * DHALF];  // split-K partials of E @ V'

// exp via exp2 range reduction, pure FMA/ALU (avoids slow MUFU path)
__device__ __forceinline__ float fast_exp(float x) {
    float y = x * 1.44269504088896f;       // x * log2(e)
    float i = rintf(y);
    float t = (y - i) * 0.69314718055995f; // f * ln2, |t| <= 0.3466
    float p = 1.3888889e-3f;               // 1/720
    p = fmaf(p, t, 8.3333333e-3f);         // 1/120
    p = fmaf(p, t, 4.1666667e-2f);         // 1/24
    p = fmaf(p, t, 1.6666667e-1f);         // 1/6
    p = fmaf(p, t, 0.5f);
    p = fmaf(p, t, 1.0f);
    p = fmaf(p, t, 1.0f);
    int ii = (int)i;
    return p * __int_as_float((ii + 127) << 23);
}

__device__ __forceinline__ void mma16(float* d, const unsigned* a, const unsigned* b) {
    asm volatile(
        "mma.sync.aligned.m16n8k16.row.col.f32.f16.f16.f32 "
        "{%0,%1,%2,%3}, {%4,%5,%6,%7}, {%8,%9}, {%0,%1,%2,%3};\n"
        : "+f"(d[0]), "+f"(d[1]), "+f"(d[2]), "+f"(d[3])
        : "r"(a[0]), "r"(a[1]), "r"(a[2]), "r"(a[3]), "r"(b[0]), "r"(b[1]));
}

__device__ __forceinline__ void cpa16(__half* dst, const __half* src) {
    unsigned d = (unsigned)__cvta_generic_to_shared(dst);
    asm volatile("cp.async.cg.shared.global [%0], [%1], 16;\n" :: "r"(d), "l"(src));
}
#define CP_COMMIT()  asm volatile("cp.async.commit_group;\n" ::: "memory")
#define CP_WAIT2()   asm volatile("cp.async.wait_group 2;\n" ::: "memory")

// ---------------------------------------------------------------------------
// fp16 GEMM, 4-stage cp.async pipeline, ONE barrier per k-tile.
//   C[M x Nc] = f(A[M x K] @ B^T), A row-major [m][k], B row-major [n][k].
//   Tile 128x256, kTile 32, 256 threads (8 warps, warp tile 64x64).
//   EPI: 0 = half(acc + bias)            (C half, ld ldc)
//        1 = half(fast_exp(acc*scale))   (C half)
//        2 = float acc                   (C float, split-K plane z*c_split)
//        3 = half(acc), TRANSPOSED store C'[n][m] ld NN
// ---------------------------------------------------------------------------
#define ASTH 40                 // A smem row stride in halfs (32 + 8 pad)
#define BSTH 40                 // B smem row stride in halfs
#define A_STAGE_H (128 * ASTH)  // 5120 halfs
#define B_STAGE_H (256 * BSTH)  // 10240 halfs
#define SMEM_HALFS (4 * (A_STAGE_H + B_STAGE_H))
static_assert(SMEM_HALFS * 2 <= 227 * 1024, "smem");

template<int EPI>
__global__ __launch_bounds__(256, 1) void gemm_h(
    const __half* __restrict__ A, int lda,
    const __half* __restrict__ B, int ldb,
    void* __restrict__ Cv, int ldc, size_t c_split,
    int Kchunk, const float* __restrict__ bias, float scale)
{
    extern __shared__ __half sm[];
    __half* Asm = sm;                       // 4 stages
    __half* Bsm = sm + 4 * A_STAGE_H;

    const int tid  = threadIdx.x;
    const int lane = tid & 31;
    const int warp = tid >> 5;
    const int wm   = warp >> 2;
    const int wn   = warp & 3;
    const int gid  = lane >> 2;
    const int tig  = lane & 3;
    const int rb   = blockIdx.y * 128;
    const int cb   = blockIdx.x * 256;
    const int kbase = blockIdx.z * Kchunk;

    float acc[4][8][4];
#pragma unroll
    for (int mt = 0; mt < 4; mt++)
#pragma unroll
        for (int nt = 0; nt < 8; nt++)
#pragma unroll
            for (int i = 0; i < 4; i++) acc[mt][nt][i] = 0.f;

    auto issueLoads = [&](int slot, int k0) {
        __half* As = Asm + slot * A_STAGE_H;
        __half* Bs = Bsm + slot * B_STAGE_H;
#pragma unroll
        for (int i = 0; i < 2; i++) {         // A: 128 rows x 32 halfs
            int q = tid + i * 256;
            int r = q >> 2, c = (q & 3) * 8;
            cpa16(&As[r * ASTH + c], &A[(size_t)(rb + r) * lda + kbase + k0 + c]);
        }
#pragma unroll
        for (int i = 0; i < 4; i++) {         // B: 256 n-rows x 32 halfs
            int q = tid + i * 256;
            int n = q >> 2, c = (q & 3) * 8;
            cpa16(&Bs[n * BSTH + c], &B[(size_t)(cb + n) * ldb + kbase + k0 + c]);
        }
    };

    const int NITER = Kchunk / 32;
    issueLoads(0, 0);  CP_COMMIT();
    issueLoads(1, 32); CP_COMMIT();
    issueLoads(2, 64); CP_COMMIT();

    for (int it = 0; it < NITER; ++it) {
        CP_WAIT2();
        __syncthreads();                      // slot (it-1)&3 free for reuse below
        int nx = it + 3;
        if (nx < NITER) issueLoads(nx & 3, nx * 32);
        CP_COMMIT();

        const unsigned* Au = (const unsigned*)(Asm + (it & 3) * A_STAGE_H);
        const unsigned* Bu = (const unsigned*)(Bsm + (it & 3) * B_STAGE_H);
        constexpr int ASU = ASTH / 2;         // 20 uints per row
        constexpr int BSU = BSTH / 2;
#pragma unroll
        for (int ko = 0; ko < 16; ko += 8) {  // two k16 steps per tile
            unsigned af[4][4], bf[8][2];
#pragma unroll
            for (int mt = 0; mt < 4; mt++) {
                int r0 = wm * 64 + mt * 16 + gid;
                af[mt][0] = Au[r0 * ASU + ko + tig];
                af[mt][1] = Au[(r0 + 8) * ASU + ko + tig];
                af[mt][2] = Au[r0 * ASU + ko + tig + 4];
                af[mt][3] = Au[(r0 + 8) * ASU + ko + tig + 4];
            }
#pragma unroll
            for (int nt = 0; nt < 8; nt++) {
                int c0 = wn * 64 + nt * 8 + gid;
                bf[nt][0] = Bu[c0 * BSU + ko + tig];
                bf[nt][1] = Bu[c0 * BSU + ko + tig + 4];
            }
#pragma unroll
            for (int mt = 0; mt < 4; mt++)
#pragma unroll
                for (int nt = 0; nt < 8; nt++)
                    mma16(acc[mt][nt], af[mt], bf[nt]);
        }
    }

    // ----- epilogue -----
#pragma unroll
    for (int mt = 0; mt < 4; mt++) {
#pragma unroll
        for (int nt = 0; nt < 8; nt++) {
            int r0 = rb + wm * 64 + mt * 16 + gid;
            int c0 = cb + wn * 64 + nt * 8 + 2 * tig;
            float v0 = acc[mt][nt][0], v1 = acc[mt][nt][1];
            float v2 = acc[mt][nt][2], v3 = acc[mt][nt][3];
            if (EPI == 0) {
                __half* C = (__half*)Cv;
                float b0 = bias[c0], b1v = bias[c0 + 1];
                *(__half2*)&C[(size_t)r0 * ldc + c0] =
                    __floats2half2_rn(v0 + b0, v1 + b1v);
                *(__half2*)&C[(size_t)(r0 + 8) * ldc + c0] =
                    __floats2half2_rn(v2 + b0, v3 + b1v);
            } else if (EPI == 1) {
                __half* C = (__half*)Cv;
                *(__half2*)&C[(size_t)r0 * ldc + c0] =
                    __floats2half2_rn(fast_exp(v0 * scale), fast_exp(v1 * scale));
                *(__half2*)&C[(size_t)(r0 + 8) * ldc + c0] =
                    __floats2half2_rn(fast_exp(v2 * scale), fast_exp(v3 * scale));
            } else if (EPI == 2) {
                float* C = (float*)Cv + blockIdx.z * c_split;
                *(float2*)&C[(size_t)r0 * ldc + c0]       = make_float2(v0, v1);
                *(float2*)&C[(size_t)(r0 + 8) * ldc + c0] = make_float2(v2, v3);
            } else {  // EPI 3: transposed half store C'[n][m], ld NN
                __half* C = (__half*)Cv;
                C[(size_t)c0 * NN + r0]           = __float2half_rn(v0);
                C[(size_t)(c0 + 1) * NN + r0]     = __float2half_rn(v1);
                C[(size_t)c0 * NN + r0 + 8]       = __float2half_rn(v2);
                C[(size_t)(c0 + 1) * NN + r0 + 8] = __float2half_rn(v3);
            }
        }
    }
}

// --------------------------- prep kernels -----------------------------------
__global__ void xprep_h(const float* __restrict__ x, __half* __restrict__ o, int n4)
{
    int i = blockIdx.x * blockDim.x + threadIdx.x;
    if (i < n4) {
        float4 v = ((const float4*)x)[i];
        __half2* o2 = (__half2*)o;
        o2[i * 2]     = __floats2half2_rn(v.x, v.y);
        o2[i * 2 + 1] = __floats2half2_rn(v.z, v.w);
    }
}

// wqkvT[c][r] = W*[r][c'], c in [0,1536), r in [0,1024)
__global__ void pack_wqkvT(const float* __restrict__ Wq, const float* __restrict__ Wk,
                           const float* __restrict__ Wv,
                           const float* __restrict__ bq, const float* __restrict__ bk,
                           const float* __restrict__ bv)
{
    int i = blockIdx.x * blockDim.x + threadIdx.x;
    if (i < 1536 * INDIM) {
        int c = i / INDIM, r = i % INDIM;
        float v = (c < 512) ? Wq[r * 512 + c]
               : (c < 1024) ? Wk[r * 512 + c - 512]
                            : Wv[r * 512 + c - 1024];
        g_wqkvT[i] = __float2half_rn(v);
    }
    if (i < 1536)
        g_bqkv[i] = (i < 512) ? bq[i] : (i < 1024) ? bk[i - 512] : bv[i - 1024];
}

// w1T[n][k] = W1[k][n]
__global__ void pack_w1T(const float* __restrict__ W1)
{
    int i = blockIdx.x * blockDim.x + threadIdx.x;
    if (i < DHALF * DD) {
        int n = i / DD, k = i % DD;
        g_w1T[i] = __float2half_rn(W1[k * DHALF + n]);
    }
}

// row sums of half E (one block per row)
__global__ __launch_bounds__(256) void rowsum()
{
    const int row = blockIdx.x;
    const int t = threadIdx.x;
    const __half2* e = (const __half2*)(g_eh + (size_t)row * NN);
    __shared__ float red[256];
    float s = 0.f;
#pragma unroll
    for (int i = 0; i < NN / 2 / 256; i++) {
        float2 v = __half22float2(e[t + i * 256]);
        s += v.x + v.y;
    }
    red[t] = s; __syncthreads();
    for (int w = 128; w > 0; w >>= 1) {
        if (t < w) red[t] += red[t + w];
        __syncthreads();
    }
    if (t == 0) g_r[row] = red[0];
}

// sum split-K partials, normalize, relu(+b1), dot W2 -> score
__global__ __launch_bounds__(256) void pv_reduce_score(
    const float* __restrict__ b1, const float* __restrict__ W2,
    const float* __restrict__ b2, float* __restrict__ out)
{
    const int row = blockIdx.x;
    const int t = threadIdx.x;
    __shared__ float red[256];
    float s = 0.f;
#pragma unroll
    for (int z = 0; z < 8; z++)
        s += g_u[(size_t)z * NN * DHALF + (size_t)row * DHALF + t];
    float h = fmaxf(s / g_r[row] + b1[t], 0.f);
    red[t] = h * W2[t];
    __syncthreads();
    for (int w = 128; w > 0; w >>= 1) {
        if (t < w) red[t] += red[t + w];
        __syncthreads();
    }
    if (t == 0) out[row] = red[0] + b2[0];
}

// ---------------------------------------------------------------------------
extern "C" void kernel_launch(void* const* d_in, const int* in_sizes, int n_in,
                              void* d_out, int out_size)
{
    const float* x  = (const float*)d_in[0];
    const float* Wq = (const float*)d_in[1];
    const float* bq = (const float*)d_in[2];
    const float* Wk = (const float*)d_in[3];
    const float* bk = (const float*)d_in[4];
    const float* Wv = (const float*)d_in[5];
    const float* bv = (const float*)d_in[6];
    const float* W1 = (const float*)d_in[7];
    const float* b1 = (const float*)d_in[8];
    const float* W2 = (const float*)d_in[9];
    const float* b2 = (const float*)d_in[10];
    float* out = (float*)d_out;

    __half *pxh, *pwqkvT, *pw1T, *pqkvh, *pvpT, *peh;
    float *pbqkv, *pu;
    cudaGetSymbolAddress((void**)&pxh,    g_xh);
    cudaGetSymbolAddress((void**)&pwqkvT, g_wqkvT);
    cudaGetSymbolAddress((void**)&pw1T,   g_w1T);
    cudaGetSymbolAddress((void**)&pqkvh,  g_qkvh);
    cudaGetSymbolAddress((void**)&pvpT,   g_vpT);
    cudaGetSymbolAddress((void**)&peh,    g_eh);
    cudaGetSymbolAddress((void**)&pbqkv,  g_bqkv);
    cudaGetSymbolAddress((void**)&pu,     g_u);

    const int SMEM = SMEM_HALFS * 2;   // 122880 bytes
    cudaFuncSetAttribute(gemm_h<0>, cudaFuncAttributeMaxDynamicSharedMemorySize, SMEM);
    cudaFuncSetAttribute(gemm_h<1>, cudaFuncAttributeMaxDynamicSharedMemorySize, SMEM);
    cudaFuncSetAttribute(gemm_h<2>, cudaFuncAttributeMaxDynamicSharedMemorySize, SMEM);
    cudaFuncSetAttribute(gemm_h<3>, cudaFuncAttributeMaxDynamicSharedMemorySize, SMEM);

    const float scale = 1.0f / sqrtf((float)DD);

    // prep
    xprep_h<<<(NN * INDIM / 4 + 255) / 256, 256>>>(x, pxh, NN * INDIM / 4);
    pack_wqkvT<<<(1536 * INDIM + 255) / 256, 256>>>(Wq, Wk, Wv, bq, bk, bv);
    pack_w1T<<<(DHALF * DD + 255) / 256, 256>>>(W1);

    // QKV: x[8192,1024] @ wqkvT[1536,1024]^T + bias -> qkv half
    gemm_h<0><<<dim3(6, 64), 256, SMEM>>>(
        pxh, INDIM, pwqkvT, INDIM, pqkvh, 1536, 0, INDIM, pbqkv, 1.f);

    // V' = V @ W1, stored transposed: vpT[256][8192]
    gemm_h<3><<<dim3(1, 64), 256, SMEM>>>(
        pqkvh + 1024, 1536, pw1T, DD, pvpT, 0, 0, DD, nullptr, 1.f);

    // E = exp((Q @ K^T) * scale), half
    gemm_h<1><<<dim3(32, 64), 256, SMEM>>>(
        pqkvh, 1536, pqkvh + 512, 1536, peh, NN, 0, DD, nullptr, scale);

    rowsum<<<NN, 256>>>();

    // U_z = E[:, z*1024:(z+1)*1024] @ V'T[:, z*1024:(z+1)*1024]^T (split-K 8)
    gemm_h<2><<<dim3(1, 64, 8), 256, SMEM>>>(
        peh, NN, pvpT, NN, pu, DHALF, (size_t)NN * DHALF, 1024, nullptr, 1.f);

    pv_reduce_score<<<NN, 256>>>(b1, W2, b2, out);
}

// round 9
// speedup vs baseline: 6.6457x; 1.0178x over previous
#include <cuda_runtime.h>
#include <cuda_fp16.h>
#include <math.h>
#include <stdint.h>

#define NN    8192
#define INDIM 1024
#define DD    512
#define DHALF 256

// ------------------------- scratch (device globals) -------------------------
__device__ __half g_xh[NN * INDIM];             // fp16 x
__device__ __half g_wqkvT[1536 * INDIM];        // [n][k] packed [Wq|Wk|Wv]^T
__device__ float  g_bqkv[1536];
__device__ __half g_w1T[DHALF * DD];            // W1^T [256][512]
__device__ __half g_qkvh[NN * 1536];            // q|k|v fp16 (ld=1536)
__device__ __half g_vpT[DHALF * NN];            // (V @ W1)^T  [256][8192]
__device__ __half g_eh[(size_t)NN * NN];        // E = exp(S/sqrt(D)) fp16
__device__ float  g_r[NN];                      // row sums of E
__device__ float  g_u[8 * (size_t)NN * DHALF];  // split-K partials of E @ V'

// exp via exp2 range reduction, pure FMA/ALU (avoids MUFU serialization)
__device__ __forceinline__ float fast_exp(float x) {
    float y = x * 1.44269504088896f;
    float i = rintf(y);
    float t = (y - i) * 0.69314718055995f;
    float p = 1.3888889e-3f;
    p = fmaf(p, t, 8.3333333e-3f);
    p = fmaf(p, t, 4.1666667e-2f);
    p = fmaf(p, t, 1.6666667e-1f);
    p = fmaf(p, t, 0.5f);
    p = fmaf(p, t, 1.0f);
    p = fmaf(p, t, 1.0f);
    return p * __int_as_float(((int)i + 127) << 23);
}

__device__ __forceinline__ void mma16(float* d, const unsigned* a, const unsigned* b) {
    asm volatile(
        "mma.sync.aligned.m16n8k16.row.col.f32.f16.f16.f32 "
        "{%0,%1,%2,%3}, {%4,%5,%6,%7}, {%8,%9}, {%0,%1,%2,%3};\n"
        : "+f"(d[0]), "+f"(d[1]), "+f"(d[2]), "+f"(d[3])
        : "r"(a[0]), "r"(a[1]), "r"(a[2]), "r"(a[3]), "r"(b[0]), "r"(b[1]));
}

__device__ __forceinline__ void ldm4(unsigned* r, uint32_t addr) {
    asm volatile(
        "ldmatrix.sync.aligned.m8n8.x4.shared.b16 {%0,%1,%2,%3}, [%4];\n"
        : "=r"(r[0]), "=r"(r[1]), "=r"(r[2]), "=r"(r[3]) : "r"(addr));
}

__device__ __forceinline__ void cpa16s(uint32_t dst, const __half* src) {
    asm volatile("cp.async.cg.shared.global [%0], [%1], 16;\n" :: "r"(dst), "l"(src));
}
#define CP_COMMIT() asm volatile("cp.async.commit_group;\n" ::: "memory")
#define CP_WAIT2()  asm volatile("cp.async.wait_group 2;\n" ::: "memory")

// ---------------------------------------------------------------------------
// fp16 mma.sync GEMM: R5's proven 4-stage cp.async pipeline; only the inner
// fragment loads changed to ldmatrix.x4 (same smem layout, 80B row stride).
//   C[M x Nc] = f(A[M x K] @ B^T), A row-major [m][k], B row-major [n][k].
//   Tile 128x256, kTile 32, 256 threads (8 warps, warp tile 64x64).
//   EPI: 0 = half(acc + bias)            (C half, ld ldc)
//        1 = half(fast_exp(acc*scale))   (C half)
//        2 = float acc                   (C float, split-K plane z*c_split)
//        3 = half(acc), TRANSPOSED store C'[n][m] ld NN
// ---------------------------------------------------------------------------
#define ROWB     80                      // smem row stride bytes (32 halfs + 8 pad)
#define A_STG_B  (128 * ROWB)            // 10240
#define B_STG_B  (256 * ROWB)            // 20480
#define STG_B    (A_STG_B + B_STG_B)     // 30720
#define NSTAGE   4
#define SMEM_BYTES (NSTAGE * STG_B)      // 122880 (same as R5)
static_assert(SMEM_BYTES <= 227 * 1024, "smem");

template<int EPI>
__global__ __launch_bounds__(256, 1) void gemm_h(
    const __half* __restrict__ A, int lda,
    const __half* __restrict__ B, int ldb,
    void* __restrict__ Cv, int ldc, size_t c_split,
    int Kchunk, const float* __restrict__ bias, float scale)
{
    extern __shared__ char smem[];
    const uint32_t sb = (uint32_t)__cvta_generic_to_shared(smem);

    const int tid  = threadIdx.x;
    const int lane = tid & 31;
    const int warp = tid >> 5;
    const int wm   = warp >> 2;          // 0..1
    const int wn   = warp & 3;           // 0..3
    const int gid  = lane >> 2;          // epilogue row
    const int tig  = lane & 3;           // epilogue col pair
    const int g8   = lane >> 3;          // ldmatrix address group 0..3
    const int lr   = lane & 7;
    const int rb   = blockIdx.y * 128;
    const int cb   = blockIdx.x * 256;
    const int kbase = blockIdx.z * Kchunk;

    // ldmatrix per-lane byte offsets (within a stage's A / B region)
    //  A x4: mat0 = m0-7@k0-7 (->a0), mat1 = m8-15@k0-7 (->a1),
    //        mat2 = m0-7@k8-15 (->a2), mat3 = m8-15@k8-15 (->a3)
    const uint32_t a_lm = (uint32_t)(wm * 64 + (g8 & 1) * 8 + lr) * ROWB
                        + (uint32_t)(g8 >> 1) * 16;
    //  B x4: mat0 = n0-7@k0-7 (->b0 even nt), mat1 = n0-7@k8-15 (->b1 even nt),
    //        mat2 = n8-15@k0-7 (->b0 odd nt), mat3 = n8-15@k8-15 (->b1 odd nt)
    const uint32_t b_lm = (uint32_t)(wn * 64 + (g8 >> 1) * 8 + lr) * ROWB
                        + (uint32_t)(g8 & 1) * 16;

    float acc[4][8][4];
#pragma unroll
    for (int mt = 0; mt < 4; mt++)
#pragma unroll
        for (int nt = 0; nt < 8; nt++)
#pragma unroll
            for (int i = 0; i < 4; i++) acc[mt][nt][i] = 0.f;

    auto issueLoads = [&](int slot, int k0) {
        uint32_t ab = sb + slot * STG_B;
        uint32_t bb = ab + A_STG_B;
#pragma unroll
        for (int i = 0; i < 2; i++) {    // A: 128 rows x 4 chunks of 16B
            int q = tid + i * 256;
            int r = q >> 2, c = q & 3;
            cpa16s(ab + r * ROWB + c * 16,
                   &A[(size_t)(rb + r) * lda + kbase + k0 + c * 8]);
        }
#pragma unroll
        for (int i = 0; i < 4; i++) {    // B: 256 n-rows x 4 chunks of 16B
            int q = tid + i * 256;
            int r = q >> 2, c = q & 3;
            cpa16s(bb + r * ROWB + c * 16,
                   &B[(size_t)(cb + r) * ldb + kbase + k0 + c * 8]);
        }
    };

    const int NIT = Kchunk / 32;
    issueLoads(0, 0);   CP_COMMIT();
    issueLoads(1, 32);  CP_COMMIT();
    issueLoads(2, 64);  CP_COMMIT();

    for (int j = 0; j < NIT; ++j) {
        CP_WAIT2();
        __syncthreads();
        int nx = j + 3;
        if (nx < NIT) issueLoads(nx & 3, nx * 32);
        CP_COMMIT();

        const uint32_t abase = sb + (j & 3) * STG_B;
        const uint32_t bbase = abase + A_STG_B;
#pragma unroll
        for (int ko = 0; ko < 2; ko++) {            // two k16 steps (bytes +32)
            unsigned af[4][4], bf[8][2];
#pragma unroll
            for (int mt = 0; mt < 4; mt++)
                ldm4(af[mt], abase + a_lm + mt * 16 * ROWB + ko * 32);
#pragma unroll
            for (int p = 0; p < 4; p++) {           // nt pairs (2p, 2p+1)
                unsigned r[4];
                ldm4(r, bbase + b_lm + p * 16 * ROWB + ko * 32);
                bf[2 * p][0] = r[0];      bf[2 * p][1] = r[1];
                bf[2 * p + 1][0] = r[2];  bf[2 * p + 1][1] = r[3];
            }
#pragma unroll
            for (int mt = 0; mt < 4; mt++)
#pragma unroll
                for (int nt = 0; nt < 8; nt++)
                    mma16(acc[mt][nt], af[mt], bf[nt]);
        }
    }

    // ----- epilogue -----
#pragma unroll
    for (int mt = 0; mt < 4; mt++) {
#pragma unroll
        for (int nt = 0; nt < 8; nt++) {
            int r0 = rb + wm * 64 + mt * 16 + gid;
            int c0 = cb + wn * 64 + nt * 8 + 2 * tig;
            float v0 = acc[mt][nt][0], v1 = acc[mt][nt][1];
            float v2 = acc[mt][nt][2], v3 = acc[mt][nt][3];
            if (EPI == 0) {
                __half* C = (__half*)Cv;
                float b0 = bias[c0], b1v = bias[c0 + 1];
                *(__half2*)&C[(size_t)r0 * ldc + c0] =
                    __floats2half2_rn(v0 + b0, v1 + b1v);
                *(__half2*)&C[(size_t)(r0 + 8) * ldc + c0] =
                    __floats2half2_rn(v2 + b0, v3 + b1v);
            } else if (EPI == 1) {
                __half* C = (__half*)Cv;
                *(__half2*)&C[(size_t)r0 * ldc + c0] =
                    __floats2half2_rn(fast_exp(v0 * scale), fast_exp(v1 * scale));
                *(__half2*)&C[(size_t)(r0 + 8) * ldc + c0] =
                    __floats2half2_rn(fast_exp(v2 * scale), fast_exp(v3 * scale));
            } else if (EPI == 2) {
                float* C = (float*)Cv + blockIdx.z * c_split;
                *(float2*)&C[(size_t)r0 * ldc + c0]       = make_float2(v0, v1);
                *(float2*)&C[(size_t)(r0 + 8) * ldc + c0] = make_float2(v2, v3);
            } else {  // EPI 3: transposed half store C'[n][m], ld NN
                __half* C = (__half*)Cv;
                C[(size_t)c0 * NN + r0]           = __float2half_rn(v0);
                C[(size_t)(c0 + 1) * NN + r0]     = __float2half_rn(v1);
                C[(size_t)c0 * NN + r0 + 8]       = __float2half_rn(v2);
                C[(size_t)(c0 + 1) * NN + r0 + 8] = __float2half_rn(v3);
            }
        }
    }
}

// --------------------------- prep / aux kernels -----------------------------
__global__ void xprep_h(const float* __restrict__ x, __half* __restrict__ o, int n4)
{
    int i = blockIdx.x * blockDim.x + threadIdx.x;
    if (i < n4) {
        float4 v = ((const float4*)x)[i];
        __half2* o2 = (__half2*)o;
        o2[i * 2]     = __floats2half2_rn(v.x, v.y);
        o2[i * 2 + 1] = __floats2half2_rn(v.z, v.w);
    }
}

__global__ void pack_wqkvT(const float* __restrict__ Wq, const float* __restrict__ Wk,
                           const float* __restrict__ Wv,
                           const float* __restrict__ bq, const float* __restrict__ bk,
                           const float* __restrict__ bv)
{
    int i = blockIdx.x * blockDim.x + threadIdx.x;
    if (i < 1536 * INDIM) {
        int c = i / INDIM, r = i % INDIM;
        float v = (c < 512) ? Wq[r * 512 + c]
               : (c < 1024) ? Wk[r * 512 + c - 512]
                            : Wv[r * 512 + c - 1024];
        g_wqkvT[i] = __float2half_rn(v);
    }
    if (i < 1536)
        g_bqkv[i] = (i < 512) ? bq[i] : (i < 1024) ? bk[i - 512] : bv[i - 1024];
}

__global__ void pack_w1T(const float* __restrict__ W1)
{
    int i = blockIdx.x * blockDim.x + threadIdx.x;
    if (i < DHALF * DD) {
        int n = i / DD, k = i % DD;
        g_w1T[i] = __float2half_rn(W1[k * DHALF + n]);
    }
}

__global__ __launch_bounds__(256) void rowsum()
{
    const int row = blockIdx.x;
    const int t = threadIdx.x;
    const __half2* e = (const __half2*)(g_eh + (size_t)row * NN);
    __shared__ float red[256];
    float s = 0.f;
#pragma unroll
    for (int i = 0; i < NN / 2 / 256; i++) {
        float2 v = __half22float2(e[t + i * 256]);
        s += v.x + v.y;
    }
    red[t] = s; __syncthreads();
    for (int w = 128; w > 0; w >>= 1) {
        if (t < w) red[t] += red[t + w];
        __syncthreads();
    }
    if (t == 0) g_r[row] = red[0];
}

__global__ __launch_bounds__(256) void pv_reduce_score(
    const float* __restrict__ b1, const float* __restrict__ W2,
    const float* __restrict__ b2, float* __restrict__ out)
{
    const int row = blockIdx.x;
    const int t = threadIdx.x;
    __shared__ float red[256];
    float s = 0.f;
#pragma unroll
    for (int z = 0; z < 8; z++)
        s += g_u[(size_t)z * NN * DHALF + (size_t)row * DHALF + t];
    float h = fmaxf(s / g_r[row] + b1[t], 0.f);
    red[t] = h * W2[t];
    __syncthreads();
    for (int w = 128; w > 0; w >>= 1) {
        if (t < w) red[t] += red[t + w];
        __syncthreads();
    }
    if (t == 0) out[row] = red[0] + b2[0];
}

// ---------------------------------------------------------------------------
extern "C" void kernel_launch(void* const* d_in, const int* in_sizes, int n_in,
                              void* d_out, int out_size)
{
    const float* x  = (const float*)d_in[0];
    const float* Wq = (const float*)d_in[1];
    const float* bq = (const float*)d_in[2];
    const float* Wk = (const float*)d_in[3];
    const float* bk = (const float*)d_in[4];
    const float* Wv = (const float*)d_in[5];
    const float* bv = (const float*)d_in[6];
    const float* W1 = (const float*)d_in[7];
    const float* b1 = (const float*)d_in[8];
    const float* W2 = (const float*)d_in[9];
    const float* b2 = (const float*)d_in[10];
    float* out = (float*)d_out;

    __half *pxh, *pwqkvT, *pw1T, *pqkvh, *pvpT, *peh;
    float *pbqkv, *pu;
    cudaGetSymbolAddress((void**)&pxh,    g_xh);
    cudaGetSymbolAddress((void**)&pwqkvT, g_wqkvT);
    cudaGetSymbolAddress((void**)&pw1T,   g_w1T);
    cudaGetSymbolAddress((void**)&pqkvh,  g_qkvh);
    cudaGetSymbolAddress((void**)&pvpT,   g_vpT);
    cudaGetSymbolAddress((void**)&peh,    g_eh);
    cudaGetSymbolAddress((void**)&pbqkv,  g_bqkv);
    cudaGetSymbolAddress((void**)&pu,     g_u);

    cudaFuncSetAttribute(gemm_h<0>, cudaFuncAttributeMaxDynamicSharedMemorySize, SMEM_BYTES);
    cudaFuncSetAttribute(gemm_h<1>, cudaFuncAttributeMaxDynamicSharedMemorySize, SMEM_BYTES);
    cudaFuncSetAttribute(gemm_h<2>, cudaFuncAttributeMaxDynamicSharedMemorySize, SMEM_BYTES);
    cudaFuncSetAttribute(gemm_h<3>, cudaFuncAttributeMaxDynamicSharedMemorySize, SMEM_BYTES);

    const float scale = 1.0f / sqrtf((float)DD);

    // prep
    xprep_h<<<(NN * INDIM / 4 + 255) / 256, 256>>>(x, pxh, NN * INDIM / 4);
    pack_wqkvT<<<(1536 * INDIM + 255) / 256, 256>>>(Wq, Wk, Wv, bq, bk, bv);
    pack_w1T<<<(DHALF * DD + 255) / 256, 256>>>(W1);

    // QKV: x[8192,1024] @ wqkvT[1536,1024]^T + bias -> qkv half
    gemm_h<0><<<dim3(6, 64), 256, SMEM_BYTES>>>(
        pxh, INDIM, pwqkvT, INDIM, pqkvh, 1536, 0, INDIM, pbqkv, 1.f);

    // V' = V @ W1, stored transposed: vpT[256][8192]
    gemm_h<3><<<dim3(1, 64), 256, SMEM_BYTES>>>(
        pqkvh + 1024, 1536, pw1T, DD, pvpT, 0, 0, DD, nullptr, 1.f);

    // E = exp((Q @ K^T) * scale), half
    gemm_h<1><<<dim3(32, 64), 256, SMEM_BYTES>>>(
        pqkvh, 1536, pqkvh + 512, 1536, peh, NN, 0, DD, nullptr, scale);

    rowsum<<<NN, 256>>>();

    // U_z = E[:, z*1024:(z+1)*1024] @ vpT[:, z-slice]^T (split-K 8)
    gemm_h<2><<<dim3(1, 64, 8), 256, SMEM_BYTES>>>(
        peh, NN, pvpT, NN, pu, DHALF, (size_t)NN * DHALF, 1024, nullptr, 1.f);

    pv_reduce_score<<<NN, 256>>>(b1, W2, b2, out);
}

// round 10
// speedup vs baseline: 6.8402x; 1.0293x over previous
#include <cuda_runtime.h>
#include <cuda_fp16.h>
#include <math.h>
#include <stdint.h>

#define NN    8192
#define INDIM 1024
#define DD    512
#define DHALF 256

// ------------------------- scratch (device globals) -------------------------
__device__ __half g_xh[NN * INDIM];             // fp16 x
__device__ __half g_wqkvT[1536 * INDIM];        // [n][k] packed [Wq|Wk|Wv]^T
__device__ float  g_bqkv[1536];
__device__ __half g_w1T[DHALF * DD];            // W1^T [256][512]
__device__ __half g_qkvh[NN * 1536];            // q|k|v fp16 (ld=1536)
__device__ __half g_vpT[DHALF * NN];            // (V @ W1)^T  [256][8192]
__device__ __half g_eh[(size_t)NN * NN];        // E = exp(S/sqrt(D)) fp16
__device__ float  g_r[NN];                      // row sums of E
__device__ float  g_u[8 * (size_t)NN * DHALF];  // split-K partials of E @ V'

// exp via exp2 range reduction, pure FMA/ALU (avoids MUFU serialization)
__device__ __forceinline__ float fast_exp(float x) {
    float y = x * 1.44269504088896f;
    float i = rintf(y);
    float t = (y - i) * 0.69314718055995f;
    float p = 1.3888889e-3f;
    p = fmaf(p, t, 8.3333333e-3f);
    p = fmaf(p, t, 4.1666667e-2f);
    p = fmaf(p, t, 1.6666667e-1f);
    p = fmaf(p, t, 0.5f);
    p = fmaf(p, t, 1.0f);
    p = fmaf(p, t, 1.0f);
    return p * __int_as_float(((int)i + 127) << 23);
}

__device__ __forceinline__ void mma16(float* d, const unsigned* a, const unsigned* b) {
    asm volatile(
        "mma.sync.aligned.m16n8k16.row.col.f32.f16.f16.f32 "
        "{%0,%1,%2,%3}, {%4,%5,%6,%7}, {%8,%9}, {%0,%1,%2,%3};\n"
        : "+f"(d[0]), "+f"(d[1]), "+f"(d[2]), "+f"(d[3])
        : "r"(a[0]), "r"(a[1]), "r"(a[2]), "r"(a[3]), "r"(b[0]), "r"(b[1]));
}

__device__ __forceinline__ void ldm4(unsigned* r, uint32_t addr) {
    asm volatile(
        "ldmatrix.sync.aligned.m8n8.x4.shared.b16 {%0,%1,%2,%3}, [%4];\n"
        : "=r"(r[0]), "=r"(r[1]), "=r"(r[2]), "=r"(r[3]) : "r"(addr));
}

__device__ __forceinline__ void cpa16s(uint32_t dst, const __half* src) {
    asm volatile("cp.async.cg.shared.global [%0], [%1], 16;\n" :: "r"(dst), "l"(src));
}
#define CP_COMMIT() asm volatile("cp.async.commit_group;\n" ::: "memory")
#define CP_WAIT2()  asm volatile("cp.async.wait_group 2;\n" ::: "memory")

// ---------------------------------------------------------------------------
// fp16 mma.sync GEMM, 4-stage cp.async pipeline, ldmatrix fragment loads.
//   512 threads = 16 warps in a 2 x 8 grid; block tile 128x256, kTile 32;
//   warp tile 64x32 (acc 64 regs/thread -> 4 warps per SMSP at full RF).
//   C[M x Nc] = f(A[M x K] @ B^T), A row-major [m][k], B row-major [n][k].
//   EPI: 0 = half(acc + bias)            (C half, ld ldc)
//        1 = half(fast_exp(acc*scale))   (C half)
//        2 = float acc                   (C float, split-K plane z*c_split)
//        3 = half(acc), TRANSPOSED store C'[n][m] ld NN
// ---------------------------------------------------------------------------
#define ROWB     80                      // smem row stride bytes (32 halfs + 8 pad)
#define A_STG_B  (128 * ROWB)            // 10240
#define B_STG_B  (256 * ROWB)            // 20480
#define STG_B    (A_STG_B + B_STG_B)     // 30720
#define NSTAGE   4
#define SMEM_BYTES (NSTAGE * STG_B)      // 122880
static_assert(SMEM_BYTES <= 227 * 1024, "smem");

template<int EPI>
__global__ __launch_bounds__(512, 1) void gemm_h(
    const __half* __restrict__ A, int lda,
    const __half* __restrict__ B, int ldb,
    void* __restrict__ Cv, int ldc, size_t c_split,
    int Kchunk, const float* __restrict__ bias, float scale)
{
    extern __shared__ char smem[];
    const uint32_t sb = (uint32_t)__cvta_generic_to_shared(smem);

    const int tid  = threadIdx.x;
    const int lane = tid & 31;
    const int warp = tid >> 5;
    const int wm   = warp >> 3;          // 0..1  (64 rows each)
    const int wn   = warp & 7;           // 0..7  (32 cols each)
    const int gid  = lane >> 2;          // epilogue row
    const int tig  = lane & 3;           // epilogue col pair
    const int g8   = lane >> 3;          // ldmatrix address group 0..3
    const int lr   = lane & 7;
    const int rb   = blockIdx.y * 128;
    const int cb   = blockIdx.x * 256;
    const int kbase = blockIdx.z * Kchunk;

    // ldmatrix per-lane byte offsets (within a stage's A / B region)
    //  A x4: mat0 = m0-7@k0-7 (->a0), mat1 = m8-15@k0-7 (->a1),
    //        mat2 = m0-7@k8-15 (->a2), mat3 = m8-15@k8-15 (->a3)
    const uint32_t a_lm = (uint32_t)(wm * 64 + (g8 & 1) * 8 + lr) * ROWB
                        + (uint32_t)(g8 >> 1) * 16;
    //  B x4: mat0 = n0-7@k0-7 (->b0 even nt), mat1 = n0-7@k8-15 (->b1 even nt),
    //        mat2 = n8-15@k0-7 (->b0 odd nt), mat3 = n8-15@k8-15 (->b1 odd nt)
    const uint32_t b_lm = (uint32_t)(wn * 32 + (g8 >> 1) * 8 + lr) * ROWB
                        + (uint32_t)(g8 & 1) * 16;

    float acc[4][4][4];
#pragma unroll
    for (int mt = 0; mt < 4; mt++)
#pragma unroll
        for (int nt = 0; nt < 4; nt++)
#pragma unroll
            for (int i = 0; i < 4; i++) acc[mt][nt][i] = 0.f;

    auto issueLoads = [&](int slot, int k0) {
        uint32_t ab = sb + slot * STG_B;
        uint32_t bb = ab + A_STG_B;
        {                                 // A: 128 rows x 4 chunks of 16B
            int r = tid >> 2, c = tid & 3;
            cpa16s(ab + r * ROWB + c * 16,
                   &A[(size_t)(rb + r) * lda + kbase + k0 + c * 8]);
        }
#pragma unroll
        for (int i = 0; i < 2; i++) {    // B: 256 n-rows x 4 chunks of 16B
            int q = tid + i * 512;
            int r = q >> 2, c = q & 3;
            cpa16s(bb + r * ROWB + c * 16,
                   &B[(size_t)(cb + r) * ldb + kbase + k0 + c * 8]);
        }
    };

    const int NIT = Kchunk / 32;
    issueLoads(0, 0);   CP_COMMIT();
    issueLoads(1, 32);  CP_COMMIT();
    issueLoads(2, 64);  CP_COMMIT();

    for (int j = 0; j < NIT; ++j) {
        CP_WAIT2();
        __syncthreads();
        int nx = j + 3;
        if (nx < NIT) issueLoads(nx & 3, nx * 32);
        CP_COMMIT();

        const uint32_t abase = sb + (j & 3) * STG_B;
        const uint32_t bbase = abase + A_STG_B;
#pragma unroll
        for (int ko = 0; ko < 2; ko++) {            // two k16 steps (bytes +32)
            unsigned af[4][4], bf[4][2];
#pragma unroll
            for (int mt = 0; mt < 4; mt++)
                ldm4(af[mt], abase + a_lm + mt * 16 * ROWB + ko * 32);
#pragma unroll
            for (int p = 0; p < 2; p++) {           // nt pairs (2p, 2p+1)
                unsigned r[4];
                ldm4(r, bbase + b_lm + p * 16 * ROWB + ko * 32);
                bf[2 * p][0] = r[0];      bf[2 * p][1] = r[1];
                bf[2 * p + 1][0] = r[2];  bf[2 * p + 1][1] = r[3];
            }
#pragma unroll
            for (int mt = 0; mt < 4; mt++)
#pragma unroll
                for (int nt = 0; nt < 4; nt++)
                    mma16(acc[mt][nt], af[mt], bf[nt]);
        }
    }

    // ----- epilogue -----
#pragma unroll
    for (int mt = 0; mt < 4; mt++) {
#pragma unroll
        for (int nt = 0; nt < 4; nt++) {
            int r0 = rb + wm * 64 + mt * 16 + gid;
            int c0 = cb + wn * 32 + nt * 8 + 2 * tig;
            float v0 = acc[mt][nt][0], v1 = acc[mt][nt][1];
            float v2 = acc[mt][nt][2], v3 = acc[mt][nt][3];
            if (EPI == 0) {
                __half* C = (__half*)Cv;
                float b0 = bias[c0], b1v = bias[c0 + 1];
                *(__half2*)&C[(size_t)r0 * ldc + c0] =
                    __floats2half2_rn(v0 + b0, v1 + b1v);
                *(__half2*)&C[(size_t)(r0 + 8) * ldc + c0] =
                    __floats2half2_rn(v2 + b0, v3 + b1v);
            } else if (EPI == 1) {
                __half* C = (__half*)Cv;
                *(__half2*)&C[(size_t)r0 * ldc + c0] =
                    __floats2half2_rn(fast_exp(v0 * scale), fast_exp(v1 * scale));
                *(__half2*)&C[(size_t)(r0 + 8) * ldc + c0] =
                    __floats2half2_rn(fast_exp(v2 * scale), fast_exp(v3 * scale));
            } else if (EPI == 2) {
                float* C = (float*)Cv + blockIdx.z * c_split;
                *(float2*)&C[(size_t)r0 * ldc + c0]       = make_float2(v0, v1);
                *(float2*)&C[(size_t)(r0 + 8) * ldc + c0] = make_float2(v2, v3);
            } else {  // EPI 3: transposed half store C'[n][m], ld NN
                __half* C = (__half*)Cv;
                C[(size_t)c0 * NN + r0]           = __float2half_rn(v0);
                C[(size_t)(c0 + 1) * NN + r0]     = __float2half_rn(v1);
                C[(size_t)c0 * NN + r0 + 8]       = __float2half_rn(v2);
                C[(size_t)(c0 + 1) * NN + r0 + 8] = __float2half_rn(v3);
            }
        }
    }
}

// --------------------------- prep / aux kernels -----------------------------
__global__ void xprep_h(const float* __restrict__ x, __half* __restrict__ o, int n4)
{
    int i = blockIdx.x * blockDim.x + threadIdx.x;
    if (i < n4) {
        float4 v = ((const float4*)x)[i];
        __half2* o2 = (__half2*)o;
        o2[i * 2]     = __floats2half2_rn(v.x, v.y);
        o2[i * 2 + 1] = __floats2half2_rn(v.z, v.w);
    }
}

__global__ void pack_wqkvT(const float* __restrict__ Wq, const float* __restrict__ Wk,
                           const float* __restrict__ Wv,
                           const float* __restrict__ bq, const float* __restrict__ bk,
                           const float* __restrict__ bv)
{
    int i = blockIdx.x * blockDim.x + threadIdx.x;
    if (i < 1536 * INDIM) {
        int c = i / INDIM, r = i % INDIM;
        float v = (c < 512) ? Wq[r * 512 + c]
               : (c < 1024) ? Wk[r * 512 + c - 512]
                            : Wv[r * 512 + c - 1024];
        g_wqkvT[i] = __float2half_rn(v);
    }
    if (i < 1536)
        g_bqkv[i] = (i < 512) ? bq[i] : (i < 1024) ? bk[i - 512] : bv[i - 1024];
}

__global__ void pack_w1T(const float* __restrict__ W1)
{
    int i = blockIdx.x * blockDim.x + threadIdx.x;
    if (i < DHALF * DD) {
        int n = i / DD, k = i % DD;
        g_w1T[i] = __float2half_rn(W1[k * DHALF + n]);
    }
}

__global__ __launch_bounds__(256) void rowsum()
{
    const int row = blockIdx.x;
    const int t = threadIdx.x;
    const __half2* e = (const __half2*)(g_eh + (size_t)row * NN);
    __shared__ float red[256];
    float s = 0.f;
#pragma unroll
    for (int i = 0; i < NN / 2 / 256; i++) {
        float2 v = __half22float2(e[t + i * 256]);
        s += v.x + v.y;
    }
    red[t] = s; __syncthreads();
    for (int w = 128; w > 0; w >>= 1) {
        if (t < w) red[t] += red[t + w];
        __syncthreads();
    }
    if (t == 0) g_r[row] = red[0];
}

__global__ __launch_bounds__(256) void pv_reduce_score(
    const float* __restrict__ b1, const float* __restrict__ W2,
    const float* __restrict__ b2, float* __restrict__ out)
{
    const int row = blockIdx.x;
    const int t = threadIdx.x;
    __shared__ float red[256];
    float s = 0.f;
#pragma unroll
    for (int z = 0; z < 8; z++)
        s += g_u[(size_t)z * NN * DHALF + (size_t)row * DHALF + t];
    float h = fmaxf(s / g_r[row] + b1[t], 0.f);
    red[t] = h * W2[t];
    __syncthreads();
    for (int w = 128; w > 0; w >>= 1) {
        if (t < w) red[t] += red[t + w];
        __syncthreads();
    }
    if (t == 0) out[row] = red[0] + b2[0];
}

// ---------------------------------------------------------------------------
extern "C" void kernel_launch(void* const* d_in, const int* in_sizes, int n_in,
                              void* d_out, int out_size)
{
    const float* x  = (const float*)d_in[0];
    const float* Wq = (const float*)d_in[1];
    const float* bq = (const float*)d_in[2];
    const float* Wk = (const float*)d_in[3];
    const float* bk = (const float*)d_in[4];
    const float* Wv = (const float*)d_in[5];
    const float* bv = (const float*)d_in[6];
    const float* W1 = (const float*)d_in[7];
    const float* b1 = (const float*)d_in[8];
    const float* W2 = (const float*)d_in[9];
    const float* b2 = (const float*)d_in[10];
    float* out = (float*)d_out;

    __half *pxh, *pwqkvT, *pw1T, *pqkvh, *pvpT, *peh;
    float *pbqkv, *pu;
    cudaGetSymbolAddress((void**)&pxh,    g_xh);
    cudaGetSymbolAddress((void**)&pwqkvT, g_wqkvT);
    cudaGetSymbolAddress((void**)&pw1T,   g_w1T);
    cudaGetSymbolAddress((void**)&pqkvh,  g_qkvh);
    cudaGetSymbolAddress((void**)&pvpT,   g_vpT);
    cudaGetSymbolAddress((void**)&peh,    g_eh);
    cudaGetSymbolAddress((void**)&pbqkv,  g_bqkv);
    cudaGetSymbolAddress((void**)&pu,     g_u);

    cudaFuncSetAttribute(gemm_h<0>, cudaFuncAttributeMaxDynamicSharedMemorySize, SMEM_BYTES);
    cudaFuncSetAttribute(gemm_h<1>, cudaFuncAttributeMaxDynamicSharedMemorySize, SMEM_BYTES);
    cudaFuncSetAttribute(gemm_h<2>, cudaFuncAttributeMaxDynamicSharedMemorySize, SMEM_BYTES);
    cudaFuncSetAttribute(gemm_h<3>, cudaFuncAttributeMaxDynamicSharedMemorySize, SMEM_BYTES);

    const float scale = 1.0f / sqrtf((float)DD);

    // prep
    xprep_h<<<(NN * INDIM / 4 + 255) / 256, 256>>>(x, pxh, NN * INDIM / 4);
    pack_wqkvT<<<(1536 * INDIM + 255) / 256, 256>>>(Wq, Wk, Wv, bq, bk, bv);
    pack_w1T<<<(DHALF * DD + 255) / 256, 256>>>(W1);

    // QKV: x[8192,1024] @ wqkvT[1536,1024]^T + bias -> qkv half
    gemm_h<0><<<dim3(6, 64), 512, SMEM_BYTES>>>(
        pxh, INDIM, pwqkvT, INDIM, pqkvh, 1536, 0, INDIM, pbqkv, 1.f);

    // V' = V @ W1, stored transposed: vpT[256][8192]
    gemm_h<3><<<dim3(1, 64), 512, SMEM_BYTES>>>(
        pqkvh + 1024, 1536, pw1T, DD, pvpT, 0, 0, DD, nullptr, 1.f);

    // E = exp((Q @ K^T) * scale), half
    gemm_h<1><<<dim3(32, 64), 512, SMEM_BYTES>>>(
        pqkvh, 1536, pqkvh + 512, 1536, peh, NN, 0, DD, nullptr, scale);

    rowsum<<<NN, 256>>>();

    // U_z = E[:, z*1024:(z+1)*1024] @ vpT[:, z-slice]^T (split-K 8)
    gemm_h<2><<<dim3(1, 64, 8), 512, SMEM_BYTES>>>(
        peh, NN, pvpT, NN, pu, DHALF, (size_t)NN * DHALF, 1024, nullptr, 1.f);

    pv_reduce_score<<<NN, 256>>>(b1, W2, b2, out);
}

// round 11
// speedup vs baseline: 7.5338x; 1.1014x over previous
#include <cuda_runtime.h>
#include <cuda_fp16.h>
#include <math.h>
#include <stdint.h>

#define NN    8192
#define INDIM 1024
#define DD    512
#define DHALF 256

// ------------------------- scratch (device globals) -------------------------
__device__ __half g_xh[NN * INDIM];             // fp16 x
__device__ __half g_wqkvT[1536 * INDIM];        // [n][k] packed [Wq|Wk|Wv]^T
__device__ float  g_bqkv[1536];
__device__ __half g_w1T[DHALF * DD];            // W1^T [256][512]
__device__ __half g_qkvh[NN * 1536];            // q|k|v fp16 (ld=1536)
__device__ __half g_vpT[DHALF * NN];            // (V @ W1)^T  [256][8192]
__device__ __half g_eh[(size_t)NN * NN];        // E = exp(S/sqrt(D)) fp16
__device__ float  g_r[NN];                      // row sums of E
__device__ float  g_u[8 * (size_t)NN * DHALF];  // split-K partials of E @ V'

// exp via exp2 range reduction, pure FMA/ALU (avoids MUFU serialization)
__device__ __forceinline__ float fast_exp(float x) {
    float y = x * 1.44269504088896f;
    float i = rintf(y);
    float t = (y - i) * 0.69314718055995f;
    float p = 1.3888889e-3f;
    p = fmaf(p, t, 8.3333333e-3f);
    p = fmaf(p, t, 4.1666667e-2f);
    p = fmaf(p, t, 1.6666667e-1f);
    p = fmaf(p, t, 0.5f);
    p = fmaf(p, t, 1.0f);
    p = fmaf(p, t, 1.0f);
    return p * __int_as_float(((int)i + 127) << 23);
}

__device__ __forceinline__ void mma16(float* d, const unsigned* a, const unsigned* b) {
    asm volatile(
        "mma.sync.aligned.m16n8k16.row.col.f32.f16.f16.f32 "
        "{%0,%1,%2,%3}, {%4,%5,%6,%7}, {%8,%9}, {%0,%1,%2,%3};\n"
        : "+f"(d[0]), "+f"(d[1]), "+f"(d[2]), "+f"(d[3])
        : "r"(a[0]), "r"(a[1]), "r"(a[2]), "r"(a[3]), "r"(b[0]), "r"(b[1]));
}

__device__ __forceinline__ void ldm4(unsigned* r, uint32_t addr) {
    asm volatile(
        "ldmatrix.sync.aligned.m8n8.x4.shared.b16 {%0,%1,%2,%3}, [%4];\n"
        : "=r"(r[0]), "=r"(r[1]), "=r"(r[2]), "=r"(r[3]) : "r"(addr));
}

__device__ __forceinline__ void cpa16s(uint32_t dst, const __half* src) {
    asm volatile("cp.async.cg.shared.global [%0], [%1], 16;\n" :: "r"(dst), "l"(src));
}
#define CP_COMMIT() asm volatile("cp.async.commit_group;\n" ::: "memory")
#define CP_WAIT2()  asm volatile("cp.async.wait_group 2;\n" ::: "memory")

// ---------------------------------------------------------------------------
// fp16 mma.sync GEMM, 4-stage cp.async pipeline, ldmatrix fragment loads.
//   Block tile 128x128, kTile 32, 256 threads = 8 warps (2 x 4), warp tile
//   64x32 (acc 64 regs/thread). __launch_bounds__(256,2) -> 2 CTAs/SM so one
//   CTA's mma stream covers the other's barrier/load phases.
//   C[M x Nc] = f(A[M x K] @ B^T), A row-major [m][k], B row-major [n][k].
//   EPI: 0 = half(acc + bias)            (C half, ld ldc)
//        1 = half(fast_exp(acc*scale))   (C half)
//        2 = float acc                   (C float, split-K plane z*c_split)
//        3 = half(acc), TRANSPOSED store C'[n][m] ld NN
// ---------------------------------------------------------------------------
#define ROWB     80                      // smem row stride bytes (32 halfs + 8 pad)
#define A_STG_B  (128 * ROWB)            // 10240
#define B_STG_B  (128 * ROWB)            // 10240
#define STG_B    (A_STG_B + B_STG_B)     // 20480
#define NSTAGE   4
#define SMEM_BYTES (NSTAGE * STG_B)      // 81920 per CTA (x2 CTAs = 163840)
static_assert(2 * SMEM_BYTES <= 227 * 1024, "smem");

template<int EPI>
__global__ __launch_bounds__(256, 2) void gemm_h(
    const __half* __restrict__ A, int lda,
    const __half* __restrict__ B, int ldb,
    void* __restrict__ Cv, int ldc, size_t c_split,
    int Kchunk, const float* __restrict__ bias, float scale)
{
    extern __shared__ char smem[];
    const uint32_t sb = (uint32_t)__cvta_generic_to_shared(smem);

    const int tid  = threadIdx.x;
    const int lane = tid & 31;
    const int warp = tid >> 5;
    const int wm   = warp >> 2;          // 0..1  (64 rows each)
    const int wn   = warp & 3;           // 0..3  (32 cols each)
    const int gid  = lane >> 2;          // epilogue row
    const int tig  = lane & 3;           // epilogue col pair
    const int g8   = lane >> 3;          // ldmatrix address group 0..3
    const int lr   = lane & 7;
    const int rb   = blockIdx.y * 128;
    const int cb   = blockIdx.x * 128;
    const int kbase = blockIdx.z * Kchunk;

    // ldmatrix per-lane byte offsets (within a stage's A / B region)
    //  A x4: mat0 = m0-7@k0-7 (->a0), mat1 = m8-15@k0-7 (->a1),
    //        mat2 = m0-7@k8-15 (->a2), mat3 = m8-15@k8-15 (->a3)
    const uint32_t a_lm = (uint32_t)(wm * 64 + (g8 & 1) * 8 + lr) * ROWB
                        + (uint32_t)(g8 >> 1) * 16;
    //  B x4: mat0 = n0-7@k0-7 (->b0 even nt), mat1 = n0-7@k8-15 (->b1 even nt),
    //        mat2 = n8-15@k0-7 (->b0 odd nt), mat3 = n8-15@k8-15 (->b1 odd nt)
    const uint32_t b_lm = (uint32_t)(wn * 32 + (g8 >> 1) * 8 + lr) * ROWB
                        + (uint32_t)(g8 & 1) * 16;

    float acc[4][4][4];
#pragma unroll
    for (int mt = 0; mt < 4; mt++)
#pragma unroll
        for (int nt = 0; nt < 4; nt++)
#pragma unroll
            for (int i = 0; i < 4; i++) acc[mt][nt][i] = 0.f;

    auto issueLoads = [&](int slot, int k0) {
        uint32_t ab = sb + slot * STG_B;
        uint32_t bb = ab + A_STG_B;
#pragma unroll
        for (int i = 0; i < 2; i++) {    // A: 128 rows x 4 chunks of 16B
            int q = tid + i * 256;
            int r = q >> 2, c = q & 3;
            cpa16s(ab + r * ROWB + c * 16,
                   &A[(size_t)(rb + r) * lda + kbase + k0 + c * 8]);
        }
#pragma unroll
        for (int i = 0; i < 2; i++) {    // B: 128 n-rows x 4 chunks of 16B
            int q = tid + i * 256;
            int r = q >> 2, c = q & 3;
            cpa16s(bb + r * ROWB + c * 16,
                   &B[(size_t)(cb + r) * ldb + kbase + k0 + c * 8]);
        }
    };

    const int NIT = Kchunk / 32;
    issueLoads(0, 0);   CP_COMMIT();
    issueLoads(1, 32);  CP_COMMIT();
    issueLoads(2, 64);  CP_COMMIT();

    for (int j = 0; j < NIT; ++j) {
        CP_WAIT2();
        __syncthreads();
        int nx = j + 3;
        if (nx < NIT) issueLoads(nx & 3, nx * 32);
        CP_COMMIT();

        const uint32_t abase = sb + (j & 3) * STG_B;
        const uint32_t bbase = abase + A_STG_B;

        // issue ALL fragment loads for both k16 steps, then all mma
        unsigned af[2][4][4], bf[2][4][2];
#pragma unroll
        for (int ko = 0; ko < 2; ko++) {
#pragma unroll
            for (int mt = 0; mt < 4; mt++)
                ldm4(af[ko][mt], abase + a_lm + mt * 16 * ROWB + ko * 32);
#pragma unroll
            for (int p = 0; p < 2; p++) {
                unsigned r[4];
                ldm4(r, bbase + b_lm + p * 16 * ROWB + ko * 32);
                bf[ko][2 * p][0] = r[0];      bf[ko][2 * p][1] = r[1];
                bf[ko][2 * p + 1][0] = r[2];  bf[ko][2 * p + 1][1] = r[3];
            }
        }
#pragma unroll
        for (int ko = 0; ko < 2; ko++)
#pragma unroll
            for (int mt = 0; mt < 4; mt++)
#pragma unroll
                for (int nt = 0; nt < 4; nt++)
                    mma16(acc[mt][nt], af[ko][mt], bf[ko][nt]);
    }

    // ----- epilogue -----
#pragma unroll
    for (int mt = 0; mt < 4; mt++) {
#pragma unroll
        for (int nt = 0; nt < 4; nt++) {
            int r0 = rb + wm * 64 + mt * 16 + gid;
            int c0 = cb + wn * 32 + nt * 8 + 2 * tig;
            float v0 = acc[mt][nt][0], v1 = acc[mt][nt][1];
            float v2 = acc[mt][nt][2], v3 = acc[mt][nt][3];
            if (EPI == 0) {
                __half* C = (__half*)Cv;
                float b0 = bias[c0], b1v = bias[c0 + 1];
                *(__half2*)&C[(size_t)r0 * ldc + c0] =
                    __floats2half2_rn(v0 + b0, v1 + b1v);
                *(__half2*)&C[(size_t)(r0 + 8) * ldc + c0] =
                    __floats2half2_rn(v2 + b0, v3 + b1v);
            } else if (EPI == 1) {
                __half* C = (__half*)Cv;
                *(__half2*)&C[(size_t)r0 * ldc + c0] =
                    __floats2half2_rn(fast_exp(v0 * scale), fast_exp(v1 * scale));
                *(__half2*)&C[(size_t)(r0 + 8) * ldc + c0] =
                    __floats2half2_rn(fast_exp(v2 * scale), fast_exp(v3 * scale));
            } else if (EPI == 2) {
                float* C = (float*)Cv + blockIdx.z * c_split;
                *(float2*)&C[(size_t)r0 * ldc + c0]       = make_float2(v0, v1);
                *(float2*)&C[(size_t)(r0 + 8) * ldc + c0] = make_float2(v2, v3);
            } else {  // EPI 3: transposed half store C'[n][m], ld NN
                __half* C = (__half*)Cv;
                C[(size_t)c0 * NN + r0]           = __float2half_rn(v0);
                C[(size_t)(c0 + 1) * NN + r0]     = __float2half_rn(v1);
                C[(size_t)c0 * NN + r0 + 8]       = __float2half_rn(v2);
                C[(size_t)(c0 + 1) * NN + r0 + 8] = __float2half_rn(v3);
            }
        }
    }
}

// --------------------------- prep / aux kernels -----------------------------
__global__ void xprep_h(const float* __restrict__ x, __half* __restrict__ o, int n4)
{
    int i = blockIdx.x * blockDim.x + threadIdx.x;
    if (i < n4) {
        float4 v = ((const float4*)x)[i];
        __half2* o2 = (__half2*)o;
        o2[i * 2]     = __floats2half2_rn(v.x, v.y);
        o2[i * 2 + 1] = __floats2half2_rn(v.z, v.w);
    }
}

__global__ void pack_wqkvT(const float* __restrict__ Wq, const float* __restrict__ Wk,
                           const float* __restrict__ Wv,
                           const float* __restrict__ bq, const float* __restrict__ bk,
                           const float* __restrict__ bv)
{
    int i = blockIdx.x * blockDim.x + threadIdx.x;
    if (i < 1536 * INDIM) {
        int c = i / INDIM, r = i % INDIM;
        float v = (c < 512) ? Wq[r * 512 + c]
               : (c < 1024) ? Wk[r * 512 + c - 512]
                            : Wv[r * 512 + c - 1024];
        g_wqkvT[i] = __float2half_rn(v);
    }
    if (i < 1536)
        g_bqkv[i] = (i < 512) ? bq[i] : (i < 1024) ? bk[i - 512] : bv[i - 1024];
}

__global__ void pack_w1T(const float* __restrict__ W1)
{
    int i = blockIdx.x * blockDim.x + threadIdx.x;
    if (i < DHALF * DD) {
        int n = i / DD, k = i % DD;
        g_w1T[i] = __float2half_rn(W1[k * DHALF + n]);
    }
}

__global__ __launch_bounds__(256) void rowsum()
{
    const int row = blockIdx.x;
    const int t = threadIdx.x;
    const __half2* e = (const __half2*)(g_eh + (size_t)row * NN);
    __shared__ float red[256];
    float s = 0.f;
#pragma unroll
    for (int i = 0; i < NN / 2 / 256; i++) {
        float2 v = __half22float2(e[t + i * 256]);
        s += v.x + v.y;
    }
    red[t] = s; __syncthreads();
    for (int w = 128; w > 0; w >>= 1) {
        if (t < w) red[t] += red[t + w];
        __syncthreads();
    }
    if (t == 0) g_r[row] = red[0];
}

__global__ __launch_bounds__(256) void pv_reduce_score(
    const float* __restrict__ b1, const float* __restrict__ W2,
    const float* __restrict__ b2, float* __restrict__ out)
{
    const int row = blockIdx.x;
    const int t = threadIdx.x;
    __shared__ float red[256];
    float s = 0.f;
#pragma unroll
    for (int z = 0; z < 8; z++)
        s += g_u[(size_t)z * NN * DHALF + (size_t)row * DHALF + t];
    float h = fmaxf(s / g_r[row] + b1[t], 0.f);
    red[t] = h * W2[t];
    __syncthreads();
    for (int w = 128; w > 0; w >>= 1) {
        if (t < w) red[t] += red[t + w];
        __syncthreads();
    }
    if (t == 0) out[row] = red[0] + b2[0];
}

// ---------------------------------------------------------------------------
extern "C" void kernel_launch(void* const* d_in, const int* in_sizes, int n_in,
                              void* d_out, int out_size)
{
    const float* x  = (const float*)d_in[0];
    const float* Wq = (const float*)d_in[1];
    const float* bq = (const float*)d_in[2];
    const float* Wk = (const float*)d_in[3];
    const float* bk = (const float*)d_in[4];
    const float* Wv = (const float*)d_in[5];
    const float* bv = (const float*)d_in[6];
    const float* W1 = (const float*)d_in[7];
    const float* b1 = (const float*)d_in[8];
    const float* W2 = (const float*)d_in[9];
    const float* b2 = (const float*)d_in[10];
    float* out = (float*)d_out;

    __half *pxh, *pwqkvT, *pw1T, *pqkvh, *pvpT, *peh;
    float *pbqkv, *pu;
    cudaGetSymbolAddress((void**)&pxh,    g_xh);
    cudaGetSymbolAddress((void**)&pwqkvT, g_wqkvT);
    cudaGetSymbolAddress((void**)&pw1T,   g_w1T);
    cudaGetSymbolAddress((void**)&pqkvh,  g_qkvh);
    cudaGetSymbolAddress((void**)&pvpT,   g_vpT);
    cudaGetSymbolAddress((void**)&peh,    g_eh);
    cudaGetSymbolAddress((void**)&pbqkv,  g_bqkv);
    cudaGetSymbolAddress((void**)&pu,     g_u);

    cudaFuncSetAttribute(gemm_h<0>, cudaFuncAttributeMaxDynamicSharedMemorySize, SMEM_BYTES);
    cudaFuncSetAttribute(gemm_h<1>, cudaFuncAttributeMaxDynamicSharedMemorySize, SMEM_BYTES);
    cudaFuncSetAttribute(gemm_h<2>, cudaFuncAttributeMaxDynamicSharedMemorySize, SMEM_BYTES);
    cudaFuncSetAttribute(gemm_h<3>, cudaFuncAttributeMaxDynamicSharedMemorySize, SMEM_BYTES);

    const float scale = 1.0f / sqrtf((float)DD);

    // prep
    xprep_h<<<(NN * INDIM / 4 + 255) / 256, 256>>>(x, pxh, NN * INDIM / 4);
    pack_wqkvT<<<(1536 * INDIM + 255) / 256, 256>>>(Wq, Wk, Wv, bq, bk, bv);
    pack_w1T<<<(DHALF * DD + 255) / 256, 256>>>(W1);

    // QKV: x[8192,1024] @ wqkvT[1536,1024]^T + bias -> qkv half
    gemm_h<0><<<dim3(12, 64), 256, SMEM_BYTES>>>(
        pxh, INDIM, pwqkvT, INDIM, pqkvh, 1536, 0, INDIM, pbqkv, 1.f);

    // V' = V @ W1, stored transposed: vpT[256][8192]
    gemm_h<3><<<dim3(2, 64), 256, SMEM_BYTES>>>(
        pqkvh + 1024, 1536, pw1T, DD, pvpT, 0, 0, DD, nullptr, 1.f);

    // E = exp((Q @ K^T) * scale), half
    gemm_h<1><<<dim3(64, 64), 256, SMEM_BYTES>>>(
        pqkvh, 1536, pqkvh + 512, 1536, peh, NN, 0, DD, nullptr, scale);

    rowsum<<<NN, 256>>>();

    // U_z = E[:, z*1024:(z+1)*1024] @ vpT[:, z-slice]^T (split-K 8)
    gemm_h<2><<<dim3(2, 64, 8), 256, SMEM_BYTES>>>(
        peh, NN, pvpT, NN, pu, DHALF, (size_t)NN * DHALF, 1024, nullptr, 1.f);

    pv_reduce_score<<<NN, 256>>>(b1, W2, b2, out);
}

// round 12
// speedup vs baseline: 8.4798x; 1.1256x over previous
#include <cuda_runtime.h>
#include <cuda_fp16.h>
#include <math.h>
#include <stdint.h>

#define NN    8192
#define INDIM 1024
#define DD    512
#define DHALF 256

// ------------------------- scratch (device globals) -------------------------
__device__ __half g_xh[NN * INDIM];             // fp16 x
__device__ __half g_wqkvT[1536 * INDIM];        // [n][k] packed [Wq|Wk|Wv]^T
__device__ float  g_bqkv[1536];
__device__ __half g_w1T[DHALF * DD];            // W1^T [256][512]
__device__ __half g_qkvh[NN * 1536];            // q|k|v fp16 (ld=1536)
__device__ __half g_vpT[DHALF * NN];            // (V @ W1)^T  [256][8192]
__device__ __half g_eh[(size_t)NN * NN];        // E = exp(S/sqrt(D)) fp16
__device__ float  g_r[NN];                      // row sums of E (atomic)
__device__ float  g_u[8 * (size_t)NN * DHALF];  // split-K partials of E @ V'

// exp via exp2 range reduction, pure FMA/ALU (avoids MUFU serialization)
__device__ __forceinline__ float fast_exp(float x) {
    float y = x * 1.44269504088896f;
    float i = rintf(y);
    float t = (y - i) * 0.69314718055995f;
    float p = 1.3888889e-3f;
    p = fmaf(p, t, 8.3333333e-3f);
    p = fmaf(p, t, 4.1666667e-2f);
    p = fmaf(p, t, 1.6666667e-1f);
    p = fmaf(p, t, 0.5f);
    p = fmaf(p, t, 1.0f);
    p = fmaf(p, t, 1.0f);
    return p * __int_as_float(((int)i + 127) << 23);
}

__device__ __forceinline__ void mma16(float* d, const unsigned* a, const unsigned* b) {
    asm volatile(
        "mma.sync.aligned.m16n8k16.row.col.f32.f16.f16.f32 "
        "{%0,%1,%2,%3}, {%4,%5,%6,%7}, {%8,%9}, {%0,%1,%2,%3};\n"
        : "+f"(d[0]), "+f"(d[1]), "+f"(d[2]), "+f"(d[3])
        : "r"(a[0]), "r"(a[1]), "r"(a[2]), "r"(a[3]), "r"(b[0]), "r"(b[1]));
}

__device__ __forceinline__ void ldm4(unsigned* r, uint32_t addr) {
    asm volatile(
        "ldmatrix.sync.aligned.m8n8.x4.shared.b16 {%0,%1,%2,%3}, [%4];\n"
        : "=r"(r[0]), "=r"(r[1]), "=r"(r[2]), "=r"(r[3]) : "r"(addr));
}

__device__ __forceinline__ void cpa16s(uint32_t dst, const __half* src) {
    asm volatile("cp.async.cg.shared.global [%0], [%1], 16;\n" :: "r"(dst), "l"(src));
}
#define CP_COMMIT() asm volatile("cp.async.commit_group;\n" ::: "memory")
#define CP_WAIT1()  asm volatile("cp.async.wait_group 1;\n" ::: "memory")

// ---------------------------------------------------------------------------
// fp16 mma.sync GEMM, 3-stage cp.async pipeline, kTile 64 (half the barriers),
// ldmatrix fragment loads double-buffered across the 4 k16 steps.
//   Block tile 128x128, 256 threads = 8 warps (2 x 4), warp tile 64x32.
//   __launch_bounds__(256,2) -> 2 CTAs/SM.
//   C[M x Nc] = f(A[M x K] @ B^T), A row-major [m][k], B row-major [n][k].
//   EPI: 0 = half(acc + bias)            (C half, ld ldc)
//        1 = half(fast_exp(acc*scale))   (C half) + atomic row-sum into g_r
//        2 = float acc                   (C float, split-K plane z*c_split)
//        3 = half(acc), TRANSPOSED store C'[n][m] ld NN
// ---------------------------------------------------------------------------
#define KT       64
#define ROWB     144                     // smem row stride bytes (64 halfs + 8 pad)
#define A_STG_B  (128 * ROWB)            // 18432
#define B_STG_B  (128 * ROWB)            // 18432
#define STG_B    (A_STG_B + B_STG_B)     // 36864
#define NSTAGE   3
#define SMEM_BYTES (NSTAGE * STG_B)      // 110592 per CTA (x2 CTAs = 221184)
static_assert(2 * SMEM_BYTES <= 227 * 1024, "smem");

template<int EPI>
__global__ __launch_bounds__(256, 2) void gemm_h(
    const __half* __restrict__ A, int lda,
    const __half* __restrict__ B, int ldb,
    void* __restrict__ Cv, int ldc, size_t c_split,
    int Kchunk, const float* __restrict__ bias, float scale)
{
    extern __shared__ char smem[];
    const uint32_t sb = (uint32_t)__cvta_generic_to_shared(smem);

    const int tid  = threadIdx.x;
    const int lane = tid & 31;
    const int warp = tid >> 5;
    const int wm   = warp >> 2;          // 0..1  (64 rows each)
    const int wn   = warp & 3;           // 0..3  (32 cols each)
    const int gid  = lane >> 2;          // epilogue row
    const int tig  = lane & 3;           // epilogue col pair
    const int g8   = lane >> 3;          // ldmatrix address group 0..3
    const int lr   = lane & 7;
    const int rb   = blockIdx.y * 128;
    const int cb   = blockIdx.x * 128;
    const int kbase = blockIdx.z * Kchunk;

    // ldmatrix per-lane byte offsets (within a stage's A / B region)
    const uint32_t a_lm = (uint32_t)(wm * 64 + (g8 & 1) * 8 + lr) * ROWB
                        + (uint32_t)(g8 >> 1) * 16;
    const uint32_t b_lm = (uint32_t)(wn * 32 + (g8 >> 1) * 8 + lr) * ROWB
                        + (uint32_t)(g8 & 1) * 16;

    float acc[4][4][4];
#pragma unroll
    for (int mt = 0; mt < 4; mt++)
#pragma unroll
        for (int nt = 0; nt < 4; nt++)
#pragma unroll
            for (int i = 0; i < 4; i++) acc[mt][nt][i] = 0.f;

    auto issueLoads = [&](int slot, int k0) {
        uint32_t ab = sb + slot * STG_B;
        uint32_t bb = ab + A_STG_B;
#pragma unroll
        for (int i = 0; i < 4; i++) {    // A: 128 rows x 8 chunks of 16B
            int q = tid + i * 256;
            int r = q >> 3, c = q & 7;
            cpa16s(ab + r * ROWB + c * 16,
                   &A[(size_t)(rb + r) * lda + kbase + k0 + c * 8]);
        }
#pragma unroll
        for (int i = 0; i < 4; i++) {    // B: 128 n-rows x 8 chunks of 16B
            int q = tid + i * 256;
            int r = q >> 3, c = q & 7;
            cpa16s(bb + r * ROWB + c * 16,
                   &B[(size_t)(cb + r) * ldb + kbase + k0 + c * 8]);
        }
    };

    const int NIT = Kchunk / KT;
    issueLoads(0, 0);   CP_COMMIT();
    issueLoads(1, KT);  CP_COMMIT();

    for (int j = 0; j < NIT; ++j) {
        CP_WAIT1();
        __syncthreads();
        int nx = j + 2;
        if (nx < NIT) issueLoads(nx % NSTAGE, nx * KT);
        CP_COMMIT();

        const uint32_t abase = sb + (j % NSTAGE) * STG_B;
        const uint32_t bbase = abase + A_STG_B;

        unsigned af[2][4][4], bf[2][4][2];
        auto ldfrag = [&](int buf, int ko) {
#pragma unroll
            for (int mt = 0; mt < 4; mt++)
                ldm4(af[buf][mt], abase + a_lm + mt * 16 * ROWB + ko * 32);
#pragma unroll
            for (int p = 0; p < 2; p++) {
                unsigned r[4];
                ldm4(r, bbase + b_lm + p * 16 * ROWB + ko * 32);
                bf[buf][2 * p][0] = r[0];      bf[buf][2 * p][1] = r[1];
                bf[buf][2 * p + 1][0] = r[2];  bf[buf][2 * p + 1][1] = r[3];
            }
        };

        ldfrag(0, 0);
#pragma unroll
        for (int ko = 0; ko < 4; ko++) {  // four k16 steps per 64-wide tile
            if (ko < 3) ldfrag((ko + 1) & 1, ko + 1);
            const int b = ko & 1;
#pragma unroll
            for (int mt = 0; mt < 4; mt++)
#pragma unroll
                for (int nt = 0; nt < 4; nt++)
                    mma16(acc[mt][nt], af[b][mt], bf[b][nt]);
        }
    }

    // ----- epilogue -----
    float rs[4][2];
    if (EPI == 1) {
#pragma unroll
        for (int mt = 0; mt < 4; mt++) { rs[mt][0] = 0.f; rs[mt][1] = 0.f; }
    }
#pragma unroll
    for (int mt = 0; mt < 4; mt++) {
#pragma unroll
        for (int nt = 0; nt < 4; nt++) {
            int r0 = rb + wm * 64 + mt * 16 + gid;
            int c0 = cb + wn * 32 + nt * 8 + 2 * tig;
            float v0 = acc[mt][nt][0], v1 = acc[mt][nt][1];
            float v2 = acc[mt][nt][2], v3 = acc[mt][nt][3];
            if (EPI == 0) {
                __half* C = (__half*)Cv;
                float b0 = bias[c0], b1v = bias[c0 + 1];
                *(__half2*)&C[(size_t)r0 * ldc + c0] =
                    __floats2half2_rn(v0 + b0, v1 + b1v);
                *(__half2*)&C[(size_t)(r0 + 8) * ldc + c0] =
                    __floats2half2_rn(v2 + b0, v3 + b1v);
            } else if (EPI == 1) {
                __half* C = (__half*)Cv;
                float e0 = fast_exp(v0 * scale), e1 = fast_exp(v1 * scale);
                float e2 = fast_exp(v2 * scale), e3 = fast_exp(v3 * scale);
                *(__half2*)&C[(size_t)r0 * ldc + c0]       = __floats2half2_rn(e0, e1);
                *(__half2*)&C[(size_t)(r0 + 8) * ldc + c0] = __floats2half2_rn(e2, e3);
                rs[mt][0] += e0 + e1;
                rs[mt][1] += e2 + e3;
            } else if (EPI == 2) {
                float* C = (float*)Cv + blockIdx.z * c_split;
                *(float2*)&C[(size_t)r0 * ldc + c0]       = make_float2(v0, v1);
                *(float2*)&C[(size_t)(r0 + 8) * ldc + c0] = make_float2(v2, v3);
            } else {  // EPI 3: transposed half store C'[n][m], ld NN
                __half* C = (__half*)Cv;
                C[(size_t)c0 * NN + r0]           = __float2half_rn(v0);
                C[(size_t)(c0 + 1) * NN + r0]     = __float2half_rn(v1);
                C[(size_t)c0 * NN + r0 + 8]       = __float2half_rn(v2);
                C[(size_t)(c0 + 1) * NN + r0 + 8] = __float2half_rn(v3);
            }
        }
    }
    if (EPI == 1) {
#pragma unroll
        for (int mt = 0; mt < 4; mt++) {
            float s0 = rs[mt][0], s1 = rs[mt][1];
            s0 += __shfl_xor_sync(0xffffffffu, s0, 1);
            s0 += __shfl_xor_sync(0xffffffffu, s0, 2);
            s1 += __shfl_xor_sync(0xffffffffu, s1, 1);
            s1 += __shfl_xor_sync(0xffffffffu, s1, 2);
            if (tig == 0) {
                int r0 = rb + wm * 64 + mt * 16 + gid;
                atomicAdd(&g_r[r0], s0);
                atomicAdd(&g_r[r0 + 8], s1);
            }
        }
    }
}

// --------------------------- prep / aux kernels -----------------------------
__global__ void xprep_h(const float* __restrict__ x, __half* __restrict__ o, int n4)
{
    int i = blockIdx.x * blockDim.x + threadIdx.x;
    if (i < n4) {
        float4 v = ((const float4*)x)[i];
        __half2* o2 = (__half2*)o;
        o2[i * 2]     = __floats2half2_rn(v.x, v.y);
        o2[i * 2 + 1] = __floats2half2_rn(v.z, v.w);
    }
}

__global__ void pack_wqkvT(const float* __restrict__ Wq, const float* __restrict__ Wk,
                           const float* __restrict__ Wv,
                           const float* __restrict__ bq, const float* __restrict__ bk,
                           const float* __restrict__ bv)
{
    int i = blockIdx.x * blockDim.x + threadIdx.x;
    if (i < 1536 * INDIM) {
        int c = i / INDIM, r = i % INDIM;
        float v = (c < 512) ? Wq[r * 512 + c]
               : (c < 1024) ? Wk[r * 512 + c - 512]
                            : Wv[r * 512 + c - 1024];
        g_wqkvT[i] = __float2half_rn(v);
    }
    if (i < 1536)
        g_bqkv[i] = (i < 512) ? bq[i] : (i < 1024) ? bk[i - 512] : bv[i - 1024];
}

__global__ void pack_w1T(const float* __restrict__ W1)
{
    int i = blockIdx.x * blockDim.x + threadIdx.x;
    if (i < DHALF * DD) {
        int n = i / DD, k = i % DD;
        g_w1T[i] = __float2half_rn(W1[k * DHALF + n]);
    }
}

__global__ void zero_r()
{
    g_r[blockIdx.x * 256 + threadIdx.x] = 0.f;
}

__global__ __launch_bounds__(256) void pv_reduce_score(
    const float* __restrict__ b1, const float* __restrict__ W2,
    const float* __restrict__ b2, float* __restrict__ out)
{
    const int row = blockIdx.x;
    const int t = threadIdx.x;
    __shared__ float red[256];
    float s = 0.f;
#pragma unroll
    for (int z = 0; z < 8; z++)
        s += g_u[(size_t)z * NN * DHALF + (size_t)row * DHALF + t];
    float h = fmaxf(s / g_r[row] + b1[t], 0.f);
    red[t] = h * W2[t];
    __syncthreads();
    for (int w = 128; w > 0; w >>= 1) {
        if (t < w) red[t] += red[t + w];
        __syncthreads();
    }
    if (t == 0) out[row] = red[0] + b2[0];
}

// ---------------------------------------------------------------------------
extern "C" void kernel_launch(void* const* d_in, const int* in_sizes, int n_in,
                              void* d_out, int out_size)
{
    const float* x  = (const float*)d_in[0];
    const float* Wq = (const float*)d_in[1];
    const float* bq = (const float*)d_in[2];
    const float* Wk = (const float*)d_in[3];
    const float* bk = (const float*)d_in[4];
    const float* Wv = (const float*)d_in[5];
    const float* bv = (const float*)d_in[6];
    const float* W1 = (const float*)d_in[7];
    const float* b1 = (const float*)d_in[8];
    const float* W2 = (const float*)d_in[9];
    const float* b2 = (const float*)d_in[10];
    float* out = (float*)d_out;

    __half *pxh, *pwqkvT, *pw1T, *pqkvh, *pvpT, *peh;
    float *pbqkv, *pu;
    cudaGetSymbolAddress((void**)&pxh,    g_xh);
    cudaGetSymbolAddress((void**)&pwqkvT, g_wqkvT);
    cudaGetSymbolAddress((void**)&pw1T,   g_w1T);
    cudaGetSymbolAddress((void**)&pqkvh,  g_qkvh);
    cudaGetSymbolAddress((void**)&pvpT,   g_vpT);
    cudaGetSymbolAddress((void**)&peh,    g_eh);
    cudaGetSymbolAddress((void**)&pbqkv,  g_bqkv);
    cudaGetSymbolAddress((void**)&pu,     g_u);

    cudaFuncSetAttribute(gemm_h<0>, cudaFuncAttributeMaxDynamicSharedMemorySize, SMEM_BYTES);
    cudaFuncSetAttribute(gemm_h<1>, cudaFuncAttributeMaxDynamicSharedMemorySize, SMEM_BYTES);
    cudaFuncSetAttribute(gemm_h<2>, cudaFuncAttributeMaxDynamicSharedMemorySize, SMEM_BYTES);
    cudaFuncSetAttribute(gemm_h<3>, cudaFuncAttributeMaxDynamicSharedMemorySize, SMEM_BYTES);

    const float scale = 1.0f / sqrtf((float)DD);

    // prep
    xprep_h<<<(NN * INDIM / 4 + 255) / 256, 256>>>(x, pxh, NN * INDIM / 4);
    pack_wqkvT<<<(1536 * INDIM + 255) / 256, 256>>>(Wq, Wk, Wv, bq, bk, bv);
    pack_w1T<<<(DHALF * DD + 255) / 256, 256>>>(W1);
    zero_r<<<NN / 256, 256>>>();

    // QKV: x[8192,1024] @ wqkvT[1536,1024]^T + bias -> qkv half
    gemm_h<0><<<dim3(12, 64), 256, SMEM_BYTES>>>(
        pxh, INDIM, pwqkvT, INDIM, pqkvh, 1536, 0, INDIM, pbqkv, 1.f);

    // V' = V @ W1, stored transposed: vpT[256][8192]
    gemm_h<3><<<dim3(2, 64), 256, SMEM_BYTES>>>(
        pqkvh + 1024, 1536, pw1T, DD, pvpT, 0, 0, DD, nullptr, 1.f);

    // E = exp((Q @ K^T) * scale), half; row sums accumulated atomically
    gemm_h<1><<<dim3(64, 64), 256, SMEM_BYTES>>>(
        pqkvh, 1536, pqkvh + 512, 1536, peh, NN, 0, DD, nullptr, scale);

    // U_z = E[:, z*1024:(z+1)*1024] @ vpT[:, z-slice]^T (split-K 8)
    gemm_h<2><<<dim3(2, 64, 8), 256, SMEM_BYTES>>>(
        peh, NN, pvpT, NN, pu, DHALF, (size_t)NN * DHALF, 1024, nullptr, 1.f);

    pv_reduce_score<<<NN, 256>>>(b1, W2, b2, out);
}

// round 14
// speedup vs baseline: 9.5896x; 1.1309x over previous
#include <cuda_runtime.h>
#include <cuda_fp16.h>
#include <math.h>
#include <stdint.h>

#define NN    8192
#define INDIM 1024
#define DD    512
#define DHALF 256

// ------------------------- scratch (device globals) -------------------------
__device__ __half g_xh[NN * INDIM];             // fp16 x
__device__ __half g_wqkvT[1536 * INDIM];        // [n][k] packed [Wq|Wk|Wv]^T
__device__ float  g_bqkv[1536];
__device__ __half g_w1T[DHALF * DD];            // W1^T [256][512]
__device__ __half g_qkvh[NN * 1536];            // q|k|v fp16 (ld=1536)
__device__ __half g_vpT[DHALF * NN];            // (V @ W1)^T  [256][8192]
__device__ __half g_eh[(size_t)NN * NN];        // E = exp(S/sqrt(D)) fp16
__device__ float  g_r[NN];                      // row sums of E (atomic)
__device__ float  g_u[8 * (size_t)NN * DHALF];  // split-K partials of E @ V'

// exp via exp2 range reduction, pure FMA/ALU (avoids MUFU serialization)
__device__ __forceinline__ float fast_exp(float x) {
    float y = x * 1.44269504088896f;
    float i = rintf(y);
    float t = (y - i) * 0.69314718055995f;
    float p = 1.3888889e-3f;
    p = fmaf(p, t, 8.3333333e-3f);
    p = fmaf(p, t, 4.1666667e-2f);
    p = fmaf(p, t, 1.6666667e-1f);
    p = fmaf(p, t, 0.5f);
    p = fmaf(p, t, 1.0f);
    p = fmaf(p, t, 1.0f);
    return p * __int_as_float(((int)i + 127) << 23);
}

__device__ __forceinline__ void mma16(float* d, const unsigned* a, const unsigned* b) {
    asm volatile(
        "mma.sync.aligned.m16n8k16.row.col.f32.f16.f16.f32 "
        "{%0,%1,%2,%3}, {%4,%5,%6,%7}, {%8,%9}, {%0,%1,%2,%3};\n"
        : "+f"(d[0]), "+f"(d[1]), "+f"(d[2]), "+f"(d[3])
        : "r"(a[0]), "r"(a[1]), "r"(a[2]), "r"(a[3]), "r"(b[0]), "r"(b[1]));
}

__device__ __forceinline__ void ldm4(unsigned* r, uint32_t addr) {
    asm volatile(
        "ldmatrix.sync.aligned.m8n8.x4.shared.b16 {%0,%1,%2,%3}, [%4];\n"
        : "=r"(r[0]), "=r"(r[1]), "=r"(r[2]), "=r"(r[3]) : "r"(addr));
}

__device__ __forceinline__ void cpa16s(uint32_t dst, const __half* src) {
    asm volatile("cp.async.cg.shared.global [%0], [%1], 16;\n" :: "r"(dst), "l"(src));
}

// ---- mbarrier machinery (Ampere-style async pipeline, per-warp drift) ------
#define MBAR_INIT(a, n) \
    asm volatile("mbarrier.init.shared.b64 [%0], %1;" :: "r"(a), "r"(n) : "memory")
#define MBAR_ARRIVE(a) \
    asm volatile("mbarrier.arrive.shared.b64 _, [%0];" :: "r"(a) : "memory")
// .noinc: async completion arrives AGAINST the initialized expected count
// (non-noinc nets to zero and deadlocks — R13's bug)
#define CPA_MBAR_ARRIVE(a) \
    asm volatile("cp.async.mbarrier.arrive.noinc.shared.b64 [%0];" :: "r"(a) : "memory")
#define MBAR_WAIT(mbar, parity) do {                                           \
    uint32_t _m = (mbar); uint32_t _p = (parity); uint32_t _done;              \
    asm volatile("{\n\t.reg .pred P;\n\t"                                      \
        "mbarrier.try_wait.parity.acquire.cta.shared::cta.b64 P, [%1], %2;\n\t"\
        "selp.b32 %0, 1, 0, P;\n\t}"                                           \
        : "=r"(_done) : "r"(_m), "r"(_p) : "memory");                          \
    while (!_done) {                                                           \
        asm volatile("{\n\t.reg .pred P;\n\t"                                  \
            "mbarrier.try_wait.parity.acquire.cta.shared::cta.b64 P, [%1], %2, 0x989680;\n\t" \
            "selp.b32 %0, 1, 0, P;\n\t}"                                       \
            : "=r"(_done) : "r"(_m), "r"(_p) : "memory");                      \
    }                                                                          \
} while (0)

// ---------------------------------------------------------------------------
// fp16 mma.sync GEMM, 3-stage cp.async pipeline tracked by mbarrier pairs:
// NO __syncthreads in the mainloop, warps drift to keep tensor pipe fed.
//   Block tile 128x128, kTile 64, 256 threads = 8 warps (2 x 4),
//   warp tile 64x32. __launch_bounds__(256,2) -> 2 CTAs/SM.
//   C[M x Nc] = f(A[M x K] @ B^T), A row-major [m][k], B row-major [n][k].
//   EPI: 0 = half(acc + bias)            (C half, ld ldc)
//        1 = half(fast_exp(acc*scale))   (C half) + atomic row-sum into g_r
//        2 = float acc                   (C float, split-K plane z*c_split)
//        3 = half(acc), TRANSPOSED store C'[n][m] ld NN
// ---------------------------------------------------------------------------
#define KT       64
#define ROWB     144                     // smem row stride bytes (64 halfs + 8 pad)
#define A_STG_B  (128 * ROWB)            // 18432
#define B_STG_B  (128 * ROWB)            // 18432
#define STG_B    (A_STG_B + B_STG_B)     // 36864
#define NSTAGE   3
#define MBAR_SP  128                     // mbar region at smem start
#define SMEM_BYTES (MBAR_SP + NSTAGE * STG_B)   // 110720/CTA (x2 = 221440)
static_assert(2 * SMEM_BYTES <= 227 * 1024, "smem");

template<int EPI>
__global__ __launch_bounds__(256, 2) void gemm_h(
    const __half* __restrict__ A, int lda,
    const __half* __restrict__ B, int ldb,
    void* __restrict__ Cv, int ldc, size_t c_split,
    int Kchunk, const float* __restrict__ bias, float scale)
{
    extern __shared__ char smem[];
    const uint32_t sb = (uint32_t)__cvta_generic_to_shared(smem);
    // mbar layout: full[s] at sb + 8*s, empty[s] at sb + 24 + 8*s
    const uint32_t mb_full  = sb;
    const uint32_t mb_empty = sb + 24;

    const int tid  = threadIdx.x;
    const int lane = tid & 31;
    const int warp = tid >> 5;
    const int wm   = warp >> 2;          // 0..1  (64 rows each)
    const int wn   = warp & 3;           // 0..3  (32 cols each)
    const int gid  = lane >> 2;          // epilogue row
    const int tig  = lane & 3;           // epilogue col pair
    const int g8   = lane >> 3;          // ldmatrix address group 0..3
    const int lr   = lane & 7;
    const int rb   = blockIdx.y * 128;
    const int cb   = blockIdx.x * 128;
    const int kbase = blockIdx.z * Kchunk;

    if (tid == 0) {
#pragma unroll
        for (int s = 0; s < NSTAGE; s++) {
            MBAR_INIT(mb_full + 8 * s, 256);
            MBAR_INIT(mb_empty + 8 * s, 256);
        }
    }
    __syncthreads();   // mbars visible before any arrive/wait

    // ldmatrix per-lane byte offsets (within a stage's A / B region)
    const uint32_t a_lm = (uint32_t)(wm * 64 + (g8 & 1) * 8 + lr) * ROWB
                        + (uint32_t)(g8 >> 1) * 16;
    const uint32_t b_lm = (uint32_t)(wn * 32 + (g8 >> 1) * 8 + lr) * ROWB
                        + (uint32_t)(g8 & 1) * 16;

    float acc[4][4][4];
#pragma unroll
    for (int mt = 0; mt < 4; mt++)
#pragma unroll
        for (int nt = 0; nt < 4; nt++)
#pragma unroll
            for (int i = 0; i < 4; i++) acc[mt][nt][i] = 0.f;

    auto issueLoads = [&](int slot, int k0) {
        uint32_t ab = sb + MBAR_SP + slot * STG_B;
        uint32_t bb = ab + A_STG_B;
#pragma unroll
        for (int i = 0; i < 4; i++) {    // A: 128 rows x 8 chunks of 16B
            int q = tid + i * 256;
            int r = q >> 3, c = q & 7;
            cpa16s(ab + r * ROWB + c * 16,
                   &A[(size_t)(rb + r) * lda + kbase + k0 + c * 8]);
        }
#pragma unroll
        for (int i = 0; i < 4; i++) {    // B: 128 n-rows x 8 chunks of 16B
            int q = tid + i * 256;
            int r = q >> 3, c = q & 7;
            cpa16s(bb + r * ROWB + c * 16,
                   &B[(size_t)(cb + r) * ldb + kbase + k0 + c * 8]);
        }
    };

    const int NIT = Kchunk / KT;
    // prime stages 0 and 1
    issueLoads(0, 0);   CPA_MBAR_ARRIVE(mb_full + 0);
    issueLoads(1, KT);  CPA_MBAR_ARRIVE(mb_full + 8);

    int fslot = 0, fphase = 0;           // consumer cursor over full[]

    for (int j = 0; j < NIT; ++j) {
        MBAR_WAIT(mb_full + 8 * fslot, fphase);

        const uint32_t abase = sb + MBAR_SP + fslot * STG_B;
        const uint32_t bbase = abase + A_STG_B;

        unsigned af[2][4][4], bf[2][4][2];
        auto ldfrag = [&](int buf, int ko) {
#pragma unroll
            for (int mt = 0; mt < 4; mt++)
                ldm4(af[buf][mt], abase + a_lm + mt * 16 * ROWB + ko * 32);
#pragma unroll
            for (int p = 0; p < 2; p++) {
                unsigned r[4];
                ldm4(r, bbase + b_lm + p * 16 * ROWB + ko * 32);
                bf[buf][2 * p][0] = r[0];      bf[buf][2 * p][1] = r[1];
                bf[buf][2 * p + 1][0] = r[2];  bf[buf][2 * p + 1][1] = r[3];
            }
        };

        ldfrag(0, 0);
#pragma unroll
        for (int ko = 0; ko < 4; ko++) {  // four k16 steps per 64-wide tile
            if (ko < 3) ldfrag((ko + 1) & 1, ko + 1);
            if (ko == 2) MBAR_ARRIVE(mb_empty + 8 * fslot);  // all frags read
            const int b = ko & 1;
#pragma unroll
            for (int mt = 0; mt < 4; mt++)
#pragma unroll
                for (int nt = 0; nt < 4; nt++)
                    mma16(acc[mt][nt], af[b][mt], bf[b][nt]);
        }

        // producer duty: refill stage j+2
        int nx = j + 2;
        if (nx < NIT) {
            int ns = nx % NSTAGE;
            if (nx >= NSTAGE)            // first write of each slot needs no wait
                MBAR_WAIT(mb_empty + 8 * ns, ((nx - NSTAGE) / NSTAGE) & 1);
            issueLoads(ns, nx * KT);
            CPA_MBAR_ARRIVE(mb_full + 8 * ns);
        }

        if (++fslot == NSTAGE) { fslot = 0; fphase ^= 1; }
    }

    // ----- epilogue -----
    float rs[4][2];
    if (EPI == 1) {
#pragma unroll
        for (int mt = 0; mt < 4; mt++) { rs[mt][0] = 0.f; rs[mt][1] = 0.f; }
    }
#pragma unroll
    for (int mt = 0; mt < 4; mt++) {
#pragma unroll
        for (int nt = 0; nt < 4; nt++) {
            int r0 = rb + wm * 64 + mt * 16 + gid;
            int c0 = cb + wn * 32 + nt * 8 + 2 * tig;
            float v0 = acc[mt][nt][0], v1 = acc[mt][nt][1];
            float v2 = acc[mt][nt][2], v3 = acc[mt][nt][3];
            if (EPI == 0) {
                __half* C = (__half*)Cv;
                float b0 = bias[c0], b1v = bias[c0 + 1];
                *(__half2*)&C[(size_t)r0 * ldc + c0] =
                    __floats2half2_rn(v0 + b0, v1 + b1v);
                *(__half2*)&C[(size_t)(r0 + 8) * ldc + c0] =
                    __floats2half2_rn(v2 + b0, v3 + b1v);
            } else if (EPI == 1) {
                __half* C = (__half*)Cv;
                float e0 = fast_exp(v0 * scale), e1 = fast_exp(v1 * scale);
                float e2 = fast_exp(v2 * scale), e3 = fast_exp(v3 * scale);
                *(__half2*)&C[(size_t)r0 * ldc + c0]       = __floats2half2_rn(e0, e1);
                *(__half2*)&C[(size_t)(r0 + 8) * ldc + c0] = __floats2half2_rn(e2, e3);
                rs[mt][0] += e0 + e1;
                rs[mt][1] += e2 + e3;
            } else if (EPI == 2) {
                float* C = (float*)Cv + blockIdx.z * c_split;
                *(float2*)&C[(size_t)r0 * ldc + c0]       = make_float2(v0, v1);
                *(float2*)&C[(size_t)(r0 + 8) * ldc + c0] = make_float2(v2, v3);
            } else {  // EPI 3: transposed half store C'[n][m], ld NN
                __half* C = (__half*)Cv;
                C[(size_t)c0 * NN + r0]           = __float2half_rn(v0);
                C[(size_t)(c0 + 1) * NN + r0]     = __float2half_rn(v1);
                C[(size_t)c0 * NN + r0 + 8]       = __float2half_rn(v2);
                C[(size_t)(c0 + 1) * NN + r0 + 8] = __float2half_rn(v3);
            }
        }
    }
    if (EPI == 1) {
#pragma unroll
        for (int mt = 0; mt < 4; mt++) {
            float s0 = rs[mt][0], s1 = rs[mt][1];
            s0 += __shfl_xor_sync(0xffffffffu, s0, 1);
            s0 += __shfl_xor_sync(0xffffffffu, s0, 2);
            s1 += __shfl_xor_sync(0xffffffffu, s1, 1);
            s1 += __shfl_xor_sync(0xffffffffu, s1, 2);
            if (tig == 0) {
                int r0 = rb + wm * 64 + mt * 16 + gid;
                atomicAdd(&g_r[r0], s0);
                atomicAdd(&g_r[r0 + 8], s1);
            }
        }
    }
}

// --------------------------- prep / aux kernels -----------------------------
__global__ void xprep_h(const float* __restrict__ x, __half* __restrict__ o, int n4)
{
    int i = blockIdx.x * blockDim.x + threadIdx.x;
    if (i < n4) {
        float4 v = ((const float4*)x)[i];
        __half2* o2 = (__half2*)o;
        o2[i * 2]     = __floats2half2_rn(v.x, v.y);
        o2[i * 2 + 1] = __floats2half2_rn(v.z, v.w);
    }
}

__global__ void pack_wqkvT(const float* __restrict__ Wq, const float* __restrict__ Wk,
                           const float* __restrict__ Wv,
                           const float* __restrict__ bq, const float* __restrict__ bk,
                           const float* __restrict__ bv)
{
    int i = blockIdx.x * blockDim.x + threadIdx.x;
    if (i < 1536 * INDIM) {
        int c = i / INDIM, r = i % INDIM;
        float v = (c < 512) ? Wq[r * 512 + c]
               : (c < 1024) ? Wk[r * 512 + c - 512]
                            : Wv[r * 512 + c - 1024];
        g_wqkvT[i] = __float2half_rn(v);
    }
    if (i < 1536)
        g_bqkv[i] = (i < 512) ? bq[i] : (i < 1024) ? bk[i - 512] : bv[i - 1024];
}

__global__ void pack_w1T(const float* __restrict__ W1)
{
    int i = blockIdx.x * blockDim.x + threadIdx.x;
    if (i < DHALF * DD) {
        int n = i / DD, k = i % DD;
        g_w1T[i] = __float2half_rn(W1[k * DHALF + n]);
    }
}

__global__ void zero_r()
{
    g_r[blockIdx.x * 256 + threadIdx.x] = 0.f;
}

__global__ __launch_bounds__(256) void pv_reduce_score(
    const float* __restrict__ b1, const float* __restrict__ W2,
    const float* __restrict__ b2, float* __restrict__ out)
{
    const int row = blockIdx.x;
    const int t = threadIdx.x;
    __shared__ float red[256];
    float s = 0.f;
#pragma unroll
    for (int z = 0; z < 8; z++)
        s += g_u[(size_t)z * NN * DHALF + (size_t)row * DHALF + t];
    float h = fmaxf(s / g_r[row] + b1[t], 0.f);
    red[t] = h * W2[t];
    __syncthreads();
    for (int w = 128; w > 0; w >>= 1) {
        if (t < w) red[t] += red[t + w];
        __syncthreads();
    }
    if (t == 0) out[row] = red[0] + b2[0];
}

// ---------------------------------------------------------------------------
extern "C" void kernel_launch(void* const* d_in, const int* in_sizes, int n_in,
                              void* d_out, int out_size)
{
    const float* x  = (const float*)d_in[0];
    const float* Wq = (const float*)d_in[1];
    const float* bq = (const float*)d_in[2];
    const float* Wk = (const float*)d_in[3];
    const float* bk = (const float*)d_in[4];
    const float* Wv = (const float*)d_in[5];
    const float* bv = (const float*)d_in[6];
    const float* W1 = (const float*)d_in[7];
    const float* b1 = (const float*)d_in[8];
    const float* W2 = (const float*)d_in[9];
    const float* b2 = (const float*)d_in[10];
    float* out = (float*)d_out;

    __half *pxh, *pwqkvT, *pw1T, *pqkvh, *pvpT, *peh;
    float *pbqkv, *pu;
    cudaGetSymbolAddress((void**)&pxh,    g_xh);
    cudaGetSymbolAddress((void**)&pwqkvT, g_wqkvT);
    cudaGetSymbolAddress((void**)&pw1T,   g_w1T);
    cudaGetSymbolAddress((void**)&pqkvh,  g_qkvh);
    cudaGetSymbolAddress((void**)&pvpT,   g_vpT);
    cudaGetSymbolAddress((void**)&peh,    g_eh);
    cudaGetSymbolAddress((void**)&pbqkv,  g_bqkv);
    cudaGetSymbolAddress((void**)&pu,     g_u);

    cudaFuncSetAttribute(gemm_h<0>, cudaFuncAttributeMaxDynamicSharedMemorySize, SMEM_BYTES);
    cudaFuncSetAttribute(gemm_h<1>, cudaFuncAttributeMaxDynamicSharedMemorySize, SMEM_BYTES);
    cudaFuncSetAttribute(gemm_h<2>, cudaFuncAttributeMaxDynamicSharedMemorySize, SMEM_BYTES);
    cudaFuncSetAttribute(gemm_h<3>, cudaFuncAttributeMaxDynamicSharedMemorySize, SMEM_BYTES);

    const float scale = 1.0f / sqrtf((float)DD);

    // prep
    xprep_h<<<(NN * INDIM / 4 + 255) / 256, 256>>>(x, pxh, NN * INDIM / 4);
    pack_wqkvT<<<(1536 * INDIM + 255) / 256, 256>>>(Wq, Wk, Wv, bq, bk, bv);
    pack_w1T<<<(DHALF * DD + 255) / 256, 256>>>(W1);
    zero_r<<<NN / 256, 256>>>();

    // QKV: x[8192,1024] @ wqkvT[1536,1024]^T + bias -> qkv half
    gemm_h<0><<<dim3(12, 64), 256, SMEM_BYTES>>>(
        pxh, INDIM, pwqkvT, INDIM, pqkvh, 1536, 0, INDIM, pbqkv, 1.f);

    // V' = V @ W1, stored transposed: vpT[256][8192]
    gemm_h<3><<<dim3(2, 64), 256, SMEM_BYTES>>>(
        pqkvh + 1024, 1536, pw1T, DD, pvpT, 0, 0, DD, nullptr, 1.f);

    // E = exp((Q @ K^T) * scale), half; row sums accumulated atomically
    gemm_h<1><<<dim3(64, 64), 256, SMEM_BYTES>>>(
        pqkvh, 1536, pqkvh + 512, 1536, peh, NN, 0, DD, nullptr, scale);

    // U_z = E[:, z*1024:(z+1)*1024] @ vpT[:, z-slice]^T (split-K 8)
    gemm_h<2><<<dim3(2, 64, 8), 256, SMEM_BYTES>>>(
        peh, NN, pvpT, NN, pu, DHALF, (size_t)NN * DHALF, 1024, nullptr, 1.f);

    pv_reduce_score<<<NN, 256>>>(b1, W2, b2, out);
}